// round 3
// baseline (speedup 1.0000x reference)
#include <cuda_runtime.h>
#include <cuda_bf16.h>
#include <cstdint>

#define BB 8
#define CC 64
#define PLANE 50176
#define CHW   (64*50176)
#define BCHW  (8*64*50176)
#define NS 28
#define KSLICE 1792   // 50176 / 28

// ---------------- scratch (static device globals; no runtime allocation) ----------------
__device__ __align__(16) __nv_bfloat16 g_Q[2ull * BCHW];   // [branch][b][c][n]
__device__ __align__(16) __nv_bfloat16 g_K[2ull * BCHW];
__device__ float g_P64[NS * 8 * 4096];    // [slice][b][64][64] lrb partial gram
__device__ float g_P8 [NS * 8 * 512];     // [slice][b][64][8]  srb partial gram
__device__ float g_G64[2 * 8 * 4096];     // [dir][b][64][64]
__device__ float g_G8 [2 * 8 * 512];      // [dir][b][64][8]
__device__ float g_R [8 * 64 * 224];      // row sums (over w)
__device__ float g_Cs[8 * 64 * 224];      // col sums (over h)
__device__ float g_S [8 * 64];            // sigmoid gates

static __device__ __forceinline__ void store4bf16(__nv_bfloat16* p, float a, float b,
                                                  float c, float d) {
    __nv_bfloat162 lo = __floats2bfloat162_rn(a, b);
    __nv_bfloat162 hi = __floats2bfloat162_rn(c, d);
    uint2 u;
    u.x = *reinterpret_cast<unsigned int*>(&lo);
    u.y = *reinterpret_cast<unsigned int*>(&hi);
    *reinterpret_cast<uint2*>(p) = u;
}

// -------- row & column sums: grid (c=64, b=8), block 224 --------
__global__ __launch_bounds__(224) void sums_kernel(const float* __restrict__ x) {
    int c = blockIdx.x, b = blockIdx.y;
    int t = threadIdx.x, lane = t & 31, wp = t >> 5;
    const float* p = x + (size_t)(b * CC + c) * PLANE;
    __shared__ float part[224][8];
    float col = 0.f;
    for (int h = 0; h < 224; ++h) {
        float v = p[h * 224 + t];
        col += v;
        float r = v;
        r += __shfl_down_sync(0xffffffffu, r, 16);
        r += __shfl_down_sync(0xffffffffu, r, 8);
        r += __shfl_down_sync(0xffffffffu, r, 4);
        r += __shfl_down_sync(0xffffffffu, r, 2);
        r += __shfl_down_sync(0xffffffffu, r, 1);
        if (lane == 0) part[h][wp] = r;
    }
    __syncthreads();
    g_Cs[(size_t)(b * CC + c) * 224 + t] = col;
    float rs = 0.f;
#pragma unroll
    for (int w = 0; w < 7; ++w) rs += part[t][w];
    g_R[(size_t)(b * CC + c) * 224 + t] = rs;
}

// -------- conv along H for q(7) and k(11), both branches. grid (49, c, b), block 256 --------
__global__ __launch_bounds__(256) void convh_kernel(
        const float* __restrict__ x,
        const float* __restrict__ lq, const float* __restrict__ lk,
        const float* __restrict__ sq, const float* __restrict__ sk) {
    int c = blockIdx.y, b = blockIdx.z;
    int t = blockIdx.x * blockDim.x + threadIdx.x;   // 0..12543
    int h = t / 56;
    int w4 = (t % 56) * 4;
    float wql[7], wqs[7], wkl[11], wks[11];
#pragma unroll
    for (int i = 0; i < 7; ++i) { wql[i] = lq[c * 7 + i]; wqs[i] = sq[c * 7 + i]; }
#pragma unroll
    for (int i = 0; i < 11; ++i) { wkl[i] = lk[c * 11 + i]; wks[i] = sk[c * 11 + i]; }
    const float* xb = x + (size_t)(b * CC + c) * PLANE;
    float ql[4] = {0,0,0,0}, qs[4] = {0,0,0,0};
    float kl[4] = {0,0,0,0}, ks[4] = {0,0,0,0};
#pragma unroll
    for (int i = 0; i < 11; ++i) {
        int hh = h + i - 5;                       // k taps: offsets -5..5
        if (hh >= 0 && hh < 224) {
            float4 v = *(const float4*)(xb + hh * 224 + w4);
            float vv[4] = {v.x, v.y, v.z, v.w};
#pragma unroll
            for (int j = 0; j < 4; ++j) { kl[j] += wkl[i] * vv[j]; ks[j] += wks[i] * vv[j]; }
            if (i >= 2 && i <= 8) {               // q taps: offsets -3..3
#pragma unroll
                for (int j = 0; j < 4; ++j) { ql[j] += wql[i-2] * vv[j]; qs[j] += wqs[i-2] * vv[j]; }
            }
        }
    }
    size_t off = (size_t)(b * CC + c) * PLANE + h * 224 + w4;
    store4bf16(g_Q + off,        ql[0], ql[1], ql[2], ql[3]);
    store4bf16(g_Q + BCHW + off, qs[0], qs[1], qs[2], qs[3]);
    store4bf16(g_K + off,        kl[0], kl[1], kl[2], kl[3]);
    store4bf16(g_K + BCHW + off, ks[0], ks[1], ks[2], ks[3]);
}

// -------- conv along W. Same grid/block as convh --------
__global__ __launch_bounds__(256) void convw_kernel(
        const float* __restrict__ x,
        const float* __restrict__ lq, const float* __restrict__ lk,
        const float* __restrict__ sq, const float* __restrict__ sk) {
    int c = blockIdx.y, b = blockIdx.z;
    int t = blockIdx.x * blockDim.x + threadIdx.x;
    int h = t / 56;
    int w4 = (t % 56) * 4;
    float wql[7], wqs[7], wkl[11], wks[11];
#pragma unroll
    for (int i = 0; i < 7; ++i) { wql[i] = lq[c * 7 + i]; wqs[i] = sq[c * 7 + i]; }
#pragma unroll
    for (int i = 0; i < 11; ++i) { wkl[i] = lk[c * 11 + i]; wks[i] = sk[c * 11 + i]; }
    const float* xr = x + (size_t)(b * CC + c) * PLANE + h * 224;
    float buf[20];                                 // x columns [w4-8, w4+11]
#pragma unroll
    for (int i = 0; i < 20; ++i) buf[i] = 0.f;
#pragma unroll
    for (int s = 0; s < 5; ++s) {
        int wb = w4 - 8 + s * 4;
        if (wb >= 0 && wb < 224) {
            float4 v = *(const float4*)(xr + wb);
            buf[s*4+0] = v.x; buf[s*4+1] = v.y; buf[s*4+2] = v.z; buf[s*4+3] = v.w;
        }
    }
    float ql[4], qs[4], kl[4], ks[4];
#pragma unroll
    for (int j = 0; j < 4; ++j) {
        float aql = 0, aqs = 0, akl = 0, aks = 0;
#pragma unroll
        for (int i = 0; i < 11; ++i) { float v = buf[j+i+3]; akl += wkl[i]*v; aks += wks[i]*v; }
#pragma unroll
        for (int i = 0; i < 7; ++i)  { float v = buf[j+i+5]; aql += wql[i]*v; aqs += wqs[i]*v; }
        ql[j] = aql; qs[j] = aqs; kl[j] = akl; ks[j] = aks;
    }
    size_t off = (size_t)(b * CC + c) * PLANE + h * 224 + w4;
    store4bf16(g_Q + off,        ql[0], ql[1], ql[2], ql[3]);
    store4bf16(g_Q + BCHW + off, qs[0], qs[1], qs[2], qs[3]);
    store4bf16(g_K + off,        kl[0], kl[1], kl[2], kl[3]);
    store4bf16(g_K + BCHW + off, ks[0], ks[1], ks[2], ks[3]);
}

// -------- lrb full 64x64 Gram over a K-slice. grid (NS, b=8), block 256 --------
__global__ __launch_bounds__(256) void gram64_kernel() {
    int slice = blockIdx.x, b = blockIdx.y;
    const __nv_bfloat16* Qb = g_Q + (size_t)b * CHW;
    const __nv_bfloat16* Kb = g_K + (size_t)b * CHW;
    __shared__ __align__(16) float Qs[16][68];
    __shared__ __align__(16) float Ksm[16][68];
    int tid = threadIdx.x;
    int c  = tid >> 2, q4 = (tid & 3) * 4;
    int tx = tid & 15, ty = tid >> 4;
    float acc[4][4] = {};
    int n0 = slice * KSLICE;
    for (int kk = 0; kk < KSLICE; kk += 16) {
        const __nv_bfloat16* qp = Qb + (size_t)c * PLANE + n0 + kk + q4;
        const __nv_bfloat16* kp = Kb + (size_t)c * PLANE + n0 + kk + q4;
        uint2 uq = *(const uint2*)qp;
        uint2 uk = *(const uint2*)kp;
        __syncthreads();
        float2 f0 = __bfloat1622float2(*(__nv_bfloat162*)&uq.x);
        float2 f1 = __bfloat1622float2(*(__nv_bfloat162*)&uq.y);
        Qs[q4+0][c] = f0.x; Qs[q4+1][c] = f0.y; Qs[q4+2][c] = f1.x; Qs[q4+3][c] = f1.y;
        f0 = __bfloat1622float2(*(__nv_bfloat162*)&uk.x);
        f1 = __bfloat1622float2(*(__nv_bfloat162*)&uk.y);
        Ksm[q4+0][c] = f0.x; Ksm[q4+1][c] = f0.y; Ksm[q4+2][c] = f1.x; Ksm[q4+3][c] = f1.y;
        __syncthreads();
#pragma unroll
        for (int ks = 0; ks < 16; ++ks) {
            float4 a  = *(const float4*)&Qs[ks][ty * 4];
            float4 bv = *(const float4*)&Ksm[ks][tx * 4];
            float av[4] = {a.x, a.y, a.z, a.w};
            float bw[4] = {bv.x, bv.y, bv.z, bv.w};
#pragma unroll
            for (int i = 0; i < 4; ++i)
#pragma unroll
                for (int j = 0; j < 4; ++j) acc[i][j] += av[i] * bw[j];
        }
    }
    float* out = g_P64 + ((size_t)slice * 8 + b) * 4096;
#pragma unroll
    for (int i = 0; i < 4; ++i)
#pragma unroll
        for (int j = 0; j < 4; ++j)
            out[(ty * 4 + i) * 64 + tx * 4 + j] = acc[i][j];
}

// -------- srb block-diagonal Gram (64 rows x 8 cols). grid (NS, b=8), block 256 --------
__global__ __launch_bounds__(256) void gram8_kernel() {
    int slice = blockIdx.x, b = blockIdx.y;
    const __nv_bfloat16* Qb = g_Q + BCHW + (size_t)b * CHW;
    const __nv_bfloat16* Kb = g_K + BCHW + (size_t)b * CHW;
    __shared__ __align__(16) float Qs[64][36];
    __shared__ __align__(16) float Ksm[64][36];
    int tid = threadIdx.x;
    int lc = tid >> 2, off8 = (tid & 3) * 8;
    int e = tid & 7, d0 = tid >> 3;   // d0 in 0..31; also handles d0+32
    float acc0 = 0.f, acc1 = 0.f;
    int n0 = slice * KSLICE;
    for (int kk = 0; kk < KSLICE; kk += 32) {
        const __nv_bfloat16* qp = Qb + (size_t)lc * PLANE + n0 + kk + off8;
        const __nv_bfloat16* kp = Kb + (size_t)lc * PLANE + n0 + kk + off8;
        uint4 uq = *(const uint4*)qp;
        uint4 uk = *(const uint4*)kp;
        __syncthreads();
        {
            float2 a0 = __bfloat1622float2(*(__nv_bfloat162*)&uq.x);
            float2 a1 = __bfloat1622float2(*(__nv_bfloat162*)&uq.y);
            float2 a2 = __bfloat1622float2(*(__nv_bfloat162*)&uq.z);
            float2 a3 = __bfloat1622float2(*(__nv_bfloat162*)&uq.w);
            float4 v0 = {a0.x, a0.y, a1.x, a1.y};
            float4 v1 = {a2.x, a2.y, a3.x, a3.y};
            *(float4*)&Qs[lc][off8]     = v0;
            *(float4*)&Qs[lc][off8 + 4] = v1;
            a0 = __bfloat1622float2(*(__nv_bfloat162*)&uk.x);
            a1 = __bfloat1622float2(*(__nv_bfloat162*)&uk.y);
            a2 = __bfloat1622float2(*(__nv_bfloat162*)&uk.z);
            a3 = __bfloat1622float2(*(__nv_bfloat162*)&uk.w);
            float4 w0 = {a0.x, a0.y, a1.x, a1.y};
            float4 w1 = {a2.x, a2.y, a3.x, a3.y};
            *(float4*)&Ksm[lc][off8]     = w0;
            *(float4*)&Ksm[lc][off8 + 4] = w1;
        }
        __syncthreads();
        int kc0 = (d0 >> 3) * 8 + e;
        int kc1 = ((d0 + 32) >> 3) * 8 + e;
#pragma unroll
        for (int ks = 0; ks < 32; ++ks) {
            acc0 += Qs[d0][ks]      * Ksm[kc0][ks];
            acc1 += Qs[d0 + 32][ks] * Ksm[kc1][ks];
        }
    }
    float* out = g_P8 + ((size_t)slice * 8 + b) * 512;
    out[d0 * 8 + e]        = acc0;
    out[(d0 + 32) * 8 + e] = acc1;
}

// -------- reduce partial grams into g_G64/g_G8 for one direction --------
__global__ __launch_bounds__(256) void reduce_kernel(int dir) {
    int idx = blockIdx.x * blockDim.x + threadIdx.x;   // 0..36863
    if (idx < 32768) {
        float s = 0.f;
        for (int sl = 0; sl < NS; ++sl) s += g_P64[(size_t)sl * 32768 + idx];
        g_G64[dir * 32768 + idx] = s;
    } else {
        int j = idx - 32768;
        if (j < 4096) {
            float s = 0.f;
            for (int sl = 0; sl < NS; ++sl) s += g_P8[(size_t)sl * 4096 + j];
            g_G8[dir * 4096 + j] = s;
        }
    }
}

// -------- finalize: vbar + softmax + mix + sigmoid. grid 8 (b), block 64 --------
__global__ __launch_bounds__(64) void finalize_kernel(
        const float* __restrict__ lvh, const float* __restrict__ lvw,
        const float* __restrict__ svh, const float* __restrict__ svw,
        const float* __restrict__ mix) {
    int b = blockIdx.x;
    int e = threadIdx.x;
    __shared__ float vb[4][64];   // 0:lrb_h 1:lrb_w 2:srb_h 3:srb_w
    // vbar from row sums (H-direction convs) and column sums (W-direction)
    for (int pass = 0; pass < 2; ++pass) {
        const float* R = (pass == 0 ? g_R : g_Cs) + (size_t)(b * 64 + e) * 224;
        const float* wl = (pass == 0 ? lvh : lvw) + e * 21;
        const float* ws = (pass == 0 ? svh : svw) + e * 21;
        float T = 0.f;
        for (int h = 0; h < 224; ++h) T += R[h];
        float head[11], tail[11];
        head[0] = 0.f; tail[0] = 0.f;
#pragma unroll
        for (int i = 1; i <= 10; ++i) { head[i] = head[i-1] + R[i-1]; tail[i] = tail[i-1] + R[224-i]; }
        float a0 = 0.f, a1 = 0.f;
#pragma unroll
        for (int t = 0; t < 21; ++t) {
            int d = t - 10;
            float clip = T - (d > 0 ? head[d] : tail[-d]);
            a0 += wl[t] * clip;
            a1 += ws[t] * clip;
        }
        vb[pass][e]     = a0 * (1.f / 50176.f);
        vb[2 + pass][e] = a1 * (1.f / 50176.f);
    }
    __syncthreads();
    int d = threadIdx.x;
    float contrib[4];
    // lrb: full 64-way softmax, scale hd^-0.5 = 1/8
#pragma unroll
    for (int dir = 0; dir < 2; ++dir) {
        const float* row = g_G64 + dir * 32768 + b * 4096 + d * 64;
        float m = -1e30f;
        for (int j = 0; j < 64; ++j) m = fmaxf(m, row[j] * 0.125f);
        float s = 0.f, dot = 0.f;
        for (int j = 0; j < 64; ++j) {
            float w = __expf(row[j] * 0.125f - m);
            s += w;
            dot += w * vb[dir][j];
        }
        contrib[dir] = dot / s;
    }
    // srb: 8-way softmax within head block, scale 8^-0.5
#pragma unroll
    for (int dir = 0; dir < 2; ++dir) {
        const float* row = g_G8 + dir * 4096 + b * 512 + d * 8;
        int base = d & ~7;
        float m = -1e30f;
#pragma unroll
        for (int j = 0; j < 8; ++j) m = fmaxf(m, row[j] * 0.35355339059327373f);
        float s = 0.f, dot = 0.f;
#pragma unroll
        for (int j = 0; j < 8; ++j) {
            float w = __expf(row[j] * 0.35355339059327373f - m);
            s += w;
            dot += w * vb[2 + dir][base + j];
        }
        contrib[2 + dir] = dot / s;
    }
    float a = mix[0] * contrib[0] + mix[1] * contrib[1]
            + mix[2] * contrib[2] + mix[3] * contrib[3];
    g_S[b * 64 + d] = 1.f / (1.f + __expf(-a));
}

// -------- apply gate: out = sigmoid(a)[b,c] * x. grid (49, 512), block 256 --------
__global__ __launch_bounds__(256) void apply_kernel(const float* __restrict__ x,
                                                    float* __restrict__ out) {
    int bc = blockIdx.y;                       // 0..511 = b*64+c
    int i = blockIdx.x * blockDim.x + threadIdx.x;   // 0..12543 (float4 within plane)
    float s = g_S[bc];
    size_t off = (size_t)bc * (PLANE / 4) + i;
    float4 v = ((const float4*)x)[off];
    v.x *= s; v.y *= s; v.z *= s; v.w *= s;
    ((float4*)out)[off] = v;
}

extern "C" void kernel_launch(void* const* d_in, const int* in_sizes, int n_in,
                              void* d_out, int out_size) {
    const float* x      = (const float*)d_in[0];
    const float* lrb_qh = (const float*)d_in[1];
    const float* lrb_qw = (const float*)d_in[2];
    const float* lrb_kh = (const float*)d_in[3];
    const float* lrb_kw = (const float*)d_in[4];
    const float* lrb_vh = (const float*)d_in[5];
    const float* lrb_vw = (const float*)d_in[6];
    const float* srb_qh = (const float*)d_in[7];
    const float* srb_qw = (const float*)d_in[8];
    const float* srb_kh = (const float*)d_in[9];
    const float* srb_kw = (const float*)d_in[10];
    const float* srb_vh = (const float*)d_in[11];
    const float* srb_vw = (const float*)d_in[12];
    const float* mix_w  = (const float*)d_in[13];
    float* out = (float*)d_out;

    sums_kernel<<<dim3(64, 8), 224>>>(x);

    convh_kernel<<<dim3(49, 64, 8), 256>>>(x, lrb_qh, lrb_kh, srb_qh, srb_kh);
    gram64_kernel<<<dim3(NS, 8), 256>>>();
    gram8_kernel<<<dim3(NS, 8), 256>>>();
    reduce_kernel<<<144, 256>>>(0);

    convw_kernel<<<dim3(49, 64, 8), 256>>>(x, lrb_qw, lrb_kw, srb_qw, srb_kw);
    gram64_kernel<<<dim3(NS, 8), 256>>>();
    gram8_kernel<<<dim3(NS, 8), 256>>>();
    reduce_kernel<<<144, 256>>>(1);

    finalize_kernel<<<8, 64>>>(lrb_vh, lrb_vw, srb_vh, srb_vw, mix_w);
    apply_kernel<<<dim3(49, 512), 256>>>(x, out);
}

// round 4
// speedup vs baseline: 1.1894x; 1.1894x over previous
#include <cuda_runtime.h>
#include <cuda_bf16.h>
#include <cstdint>

#define BB 8
#define CC 64
#define PLANE 50176
#define CHW   (64*50176)
#define BCHW  (8*64*50176)
#define NS 112
#define KSLICE 448   // 50176 / 112

// ---------------- scratch (static device globals; no runtime allocation) ----------------
__device__ __align__(16) __nv_bfloat16 g_Q[2ull * BCHW];   // [branch][b][c][n]
__device__ __align__(16) __nv_bfloat16 g_K[2ull * BCHW];
__device__ float g_P64[NS * 8 * 4096];    // [slice][b][64][64] lrb partial gram
__device__ float g_P8 [NS * 8 * 512];     // [slice][b][64][8]  srb partial gram
__device__ float g_G64[2 * 8 * 4096];     // [dir][b][64][64]
__device__ float g_G8 [2 * 8 * 512];      // [dir][b][64][8]
__device__ float g_R [8 * 64 * 224];      // row sums (over w)
__device__ float g_Cs[8 * 64 * 224];      // col sums (over h)
__device__ float g_S [8 * 64];            // sigmoid gates

static __device__ __forceinline__ void store4bf16(__nv_bfloat16* p, float a, float b,
                                                  float c, float d) {
    __nv_bfloat162 lo = __floats2bfloat162_rn(a, b);
    __nv_bfloat162 hi = __floats2bfloat162_rn(c, d);
    uint2 u;
    u.x = *reinterpret_cast<unsigned int*>(&lo);
    u.y = *reinterpret_cast<unsigned int*>(&hi);
    *reinterpret_cast<uint2*>(p) = u;
}

static __device__ __forceinline__ void unpack8(uint4 u, float* f) {
    float2 a;
    a = __bfloat1622float2(*(__nv_bfloat162*)&u.x); f[0] = a.x; f[1] = a.y;
    a = __bfloat1622float2(*(__nv_bfloat162*)&u.y); f[2] = a.x; f[3] = a.y;
    a = __bfloat1622float2(*(__nv_bfloat162*)&u.z); f[4] = a.x; f[5] = a.y;
    a = __bfloat1622float2(*(__nv_bfloat162*)&u.w); f[6] = a.x; f[7] = a.y;
}

// -------- row & column sums: grid (c=64, b=8), block 224 --------
__global__ __launch_bounds__(224) void sums_kernel(const float* __restrict__ x) {
    int c = blockIdx.x, b = blockIdx.y;
    int t = threadIdx.x, lane = t & 31, wp = t >> 5;
    const float* p = x + (size_t)(b * CC + c) * PLANE;
    __shared__ float part[224][8];
    float col = 0.f;
    for (int h = 0; h < 224; ++h) {
        float v = p[h * 224 + t];
        col += v;
        float r = v;
        r += __shfl_down_sync(0xffffffffu, r, 16);
        r += __shfl_down_sync(0xffffffffu, r, 8);
        r += __shfl_down_sync(0xffffffffu, r, 4);
        r += __shfl_down_sync(0xffffffffu, r, 2);
        r += __shfl_down_sync(0xffffffffu, r, 1);
        if (lane == 0) part[h][wp] = r;
    }
    __syncthreads();
    g_Cs[(size_t)(b * CC + c) * 224 + t] = col;
    float rs = 0.f;
#pragma unroll
    for (int w = 0; w < 7; ++w) rs += part[t][w];
    g_R[(size_t)(b * CC + c) * 224 + t] = rs;
}

// -------- conv along H for q(7) and k(11), both branches. grid (49, c, b), block 256 --------
__global__ __launch_bounds__(256) void convh_kernel(
        const float* __restrict__ x,
        const float* __restrict__ lq, const float* __restrict__ lk,
        const float* __restrict__ sq, const float* __restrict__ sk) {
    int c = blockIdx.y, b = blockIdx.z;
    int t = blockIdx.x * blockDim.x + threadIdx.x;   // 0..12543
    int h = t / 56;
    int w4 = (t % 56) * 4;
    float wql[7], wqs[7], wkl[11], wks[11];
#pragma unroll
    for (int i = 0; i < 7; ++i) { wql[i] = lq[c * 7 + i]; wqs[i] = sq[c * 7 + i]; }
#pragma unroll
    for (int i = 0; i < 11; ++i) { wkl[i] = lk[c * 11 + i]; wks[i] = sk[c * 11 + i]; }
    const float* xb = x + (size_t)(b * CC + c) * PLANE;
    float ql[4] = {0,0,0,0}, qs[4] = {0,0,0,0};
    float kl[4] = {0,0,0,0}, ks[4] = {0,0,0,0};
#pragma unroll
    for (int i = 0; i < 11; ++i) {
        int hh = h + i - 5;                       // k taps: offsets -5..5
        if (hh >= 0 && hh < 224) {
            float4 v = *(const float4*)(xb + hh * 224 + w4);
            float vv[4] = {v.x, v.y, v.z, v.w};
#pragma unroll
            for (int j = 0; j < 4; ++j) { kl[j] += wkl[i] * vv[j]; ks[j] += wks[i] * vv[j]; }
            if (i >= 2 && i <= 8) {               // q taps: offsets -3..3
#pragma unroll
                for (int j = 0; j < 4; ++j) { ql[j] += wql[i-2] * vv[j]; qs[j] += wqs[i-2] * vv[j]; }
            }
        }
    }
    size_t off = (size_t)(b * CC + c) * PLANE + h * 224 + w4;
    store4bf16(g_Q + off,        ql[0], ql[1], ql[2], ql[3]);
    store4bf16(g_Q + BCHW + off, qs[0], qs[1], qs[2], qs[3]);
    store4bf16(g_K + off,        kl[0], kl[1], kl[2], kl[3]);
    store4bf16(g_K + BCHW + off, ks[0], ks[1], ks[2], ks[3]);
}

// -------- conv along W. Same grid/block as convh --------
__global__ __launch_bounds__(256) void convw_kernel(
        const float* __restrict__ x,
        const float* __restrict__ lq, const float* __restrict__ lk,
        const float* __restrict__ sq, const float* __restrict__ sk) {
    int c = blockIdx.y, b = blockIdx.z;
    int t = blockIdx.x * blockDim.x + threadIdx.x;
    int h = t / 56;
    int w4 = (t % 56) * 4;
    float wql[7], wqs[7], wkl[11], wks[11];
#pragma unroll
    for (int i = 0; i < 7; ++i) { wql[i] = lq[c * 7 + i]; wqs[i] = sq[c * 7 + i]; }
#pragma unroll
    for (int i = 0; i < 11; ++i) { wkl[i] = lk[c * 11 + i]; wks[i] = sk[c * 11 + i]; }
    const float* xr = x + (size_t)(b * CC + c) * PLANE + h * 224;
    float buf[20];                                 // x columns [w4-8, w4+11]
#pragma unroll
    for (int i = 0; i < 20; ++i) buf[i] = 0.f;
#pragma unroll
    for (int s = 0; s < 5; ++s) {
        int wb = w4 - 8 + s * 4;
        if (wb >= 0 && wb < 224) {
            float4 v = *(const float4*)(xr + wb);
            buf[s*4+0] = v.x; buf[s*4+1] = v.y; buf[s*4+2] = v.z; buf[s*4+3] = v.w;
        }
    }
    float ql[4], qs[4], kl[4], ks[4];
#pragma unroll
    for (int j = 0; j < 4; ++j) {
        float aql = 0, aqs = 0, akl = 0, aks = 0;
#pragma unroll
        for (int i = 0; i < 11; ++i) { float v = buf[j+i+3]; akl += wkl[i]*v; aks += wks[i]*v; }
#pragma unroll
        for (int i = 0; i < 7; ++i)  { float v = buf[j+i+5]; aql += wql[i]*v; aqs += wqs[i]*v; }
        ql[j] = aql; qs[j] = aqs; kl[j] = akl; ks[j] = aks;
    }
    size_t off = (size_t)(b * CC + c) * PLANE + h * 224 + w4;
    store4bf16(g_Q + off,        ql[0], ql[1], ql[2], ql[3]);
    store4bf16(g_Q + BCHW + off, qs[0], qs[1], qs[2], qs[3]);
    store4bf16(g_K + off,        kl[0], kl[1], kl[2], kl[3]);
    store4bf16(g_K + BCHW + off, ks[0], ks[1], ks[2], ks[3]);
}

// -------- lrb full 64x64 Gram over a K-slice. grid (NS, b=8), block 256 --------
// 16x16 thread grid, 4x4 register tile each; 32-n smem chunks.
__global__ __launch_bounds__(256) void gram64_kernel() {
    int slice = blockIdx.x, b = blockIdx.y;
    const __nv_bfloat16* Qb = g_Q + (size_t)b * CHW;
    const __nv_bfloat16* Kb = g_K + (size_t)b * CHW;
    __shared__ __align__(16) float Qs[32][68];
    __shared__ __align__(16) float Ksm[32][68];
    int t = threadIdx.x;
    int lc = t >> 2, n8 = (t & 3) * 8;
    int tx = t & 15, ty = t >> 4;
    float acc[4][4] = {};
    int n0 = slice * KSLICE;
    for (int kk = 0; kk < KSLICE; kk += 32) {
        uint4 uq = *(const uint4*)(Qb + (size_t)lc * PLANE + n0 + kk + n8);
        uint4 uk = *(const uint4*)(Kb + (size_t)lc * PLANE + n0 + kk + n8);
        __syncthreads();
        float f[8];
        unpack8(uq, f);
#pragma unroll
        for (int i = 0; i < 8; ++i) Qs[n8 + i][lc] = f[i];
        unpack8(uk, f);
#pragma unroll
        for (int i = 0; i < 8; ++i) Ksm[n8 + i][lc] = f[i];
        __syncthreads();
#pragma unroll
        for (int ks = 0; ks < 32; ++ks) {
            float4 a  = *(const float4*)&Qs[ks][ty * 4];
            float4 bv = *(const float4*)&Ksm[ks][tx * 4];
            float av[4] = {a.x, a.y, a.z, a.w};
            float bw[4] = {bv.x, bv.y, bv.z, bv.w};
#pragma unroll
            for (int i = 0; i < 4; ++i)
#pragma unroll
                for (int j = 0; j < 4; ++j) acc[i][j] += av[i] * bw[j];
        }
    }
    float* out = g_P64 + ((size_t)slice * 8 + b) * 4096;
#pragma unroll
    for (int i = 0; i < 4; ++i)
#pragma unroll
        for (int j = 0; j < 4; ++j)
            out[(ty * 4 + i) * 64 + tx * 4 + j] = acc[i][j];
}

// -------- srb block-diagonal Gram: 8 heads x (8x8 tile). grid (NS, b=8), block 256 --------
// Per head: 4 threads with 4x4 register tiles (quadrants); 8-way K-split across warps;
// register partials reduced through smem at the end. 16 FMA per 2 LDS.128.
__global__ __launch_bounds__(256) void gram8_kernel() {
    int slice = blockIdx.x, b = blockIdx.y;
    const __nv_bfloat16* Qb = g_Q + BCHW + (size_t)b * CHW;
    const __nv_bfloat16* Kb = g_K + BCHW + (size_t)b * CHW;
    __shared__ __align__(16) float buf[2 * 32 * 68];   // Qs[32][68] | Ksm[32][68]; reused as red[]
    float (*Qs)[68]  = (float(*)[68])buf;
    float (*Ksm)[68] = (float(*)[68])(buf + 32 * 68);
    int t = threadIdx.x;
    int lc = t >> 2, n8 = (t & 3) * 8;
    int ksub = t >> 5;            // warp id = K-split index (0..7)
    int lane = t & 31;
    int h  = lane >> 2;           // head 0..7
    int qi = (lane >> 1) & 1, qj = lane & 1;
    float acc[4][4] = {};
    int n0 = slice * KSLICE;
    for (int kk = 0; kk < KSLICE; kk += 32) {
        uint4 uq = *(const uint4*)(Qb + (size_t)lc * PLANE + n0 + kk + n8);
        uint4 uk = *(const uint4*)(Kb + (size_t)lc * PLANE + n0 + kk + n8);
        __syncthreads();
        float f[8];
        unpack8(uq, f);
#pragma unroll
        for (int i = 0; i < 8; ++i) Qs[n8 + i][lc] = f[i];
        unpack8(uk, f);
#pragma unroll
        for (int i = 0; i < 8; ++i) Ksm[n8 + i][lc] = f[i];
        __syncthreads();
#pragma unroll
        for (int k4 = 0; k4 < 4; ++k4) {
            int ks = ksub * 4 + k4;
            float4 a  = *(const float4*)&Qs[ks][h * 8 + qi * 4];
            float4 bv = *(const float4*)&Ksm[ks][h * 8 + qj * 4];
            float av[4] = {a.x, a.y, a.z, a.w};
            float bw[4] = {bv.x, bv.y, bv.z, bv.w};
#pragma unroll
            for (int i = 0; i < 4; ++i)
#pragma unroll
                for (int j = 0; j < 4; ++j) acc[i][j] += av[i] * bw[j];
        }
    }
    // reduce the 8 K-split partials through smem
    __syncthreads();
    float* red = buf;             // [ksub][lane][16] = 4096 floats (fits in 4352)
#pragma unroll
    for (int i = 0; i < 4; ++i)
#pragma unroll
        for (int j = 0; j < 4; ++j)
            red[(ksub * 32 + lane) * 16 + i * 4 + j] = acc[i][j];
    __syncthreads();
    float* out = g_P8 + ((size_t)slice * 8 + b) * 512;
#pragma unroll
    for (int fid = t; fid < 512; fid += 256) {
        int lane_o = fid >> 4, r = fid & 15;
        int hh = lane_o >> 2, qqi = (lane_o >> 1) & 1, qqj = lane_o & 1;
        int ii = r >> 2, jj = r & 3;
        float s = 0.f;
#pragma unroll
        for (int kq = 0; kq < 8; ++kq) s += red[(kq * 32 + lane_o) * 16 + r];
        int d = hh * 8 + qqi * 4 + ii;
        int e = qqj * 4 + jj;
        out[d * 8 + e] = s;
    }
}

// -------- reduce partial grams into g_G64/g_G8 for one direction --------
__global__ __launch_bounds__(256) void reduce_kernel(int dir) {
    int idx = blockIdx.x * blockDim.x + threadIdx.x;   // 0..36863
    if (idx < 32768) {
        float s = 0.f;
        for (int sl = 0; sl < NS; ++sl) s += g_P64[(size_t)sl * 32768 + idx];
        g_G64[dir * 32768 + idx] = s;
    } else {
        int j = idx - 32768;
        if (j < 4096) {
            float s = 0.f;
            for (int sl = 0; sl < NS; ++sl) s += g_P8[(size_t)sl * 4096 + j];
            g_G8[dir * 4096 + j] = s;
        }
    }
}

// -------- finalize: vbar + softmax + mix + sigmoid. grid 8 (b), block 64 --------
__global__ __launch_bounds__(64) void finalize_kernel(
        const float* __restrict__ lvh, const float* __restrict__ lvw,
        const float* __restrict__ svh, const float* __restrict__ svw,
        const float* __restrict__ mix) {
    int b = blockIdx.x;
    int e = threadIdx.x;
    __shared__ float vb[4][64];   // 0:lrb_h 1:lrb_w 2:srb_h 3:srb_w
    for (int pass = 0; pass < 2; ++pass) {
        const float* R = (pass == 0 ? g_R : g_Cs) + (size_t)(b * 64 + e) * 224;
        const float* wl = (pass == 0 ? lvh : lvw) + e * 21;
        const float* ws = (pass == 0 ? svh : svw) + e * 21;
        float T = 0.f;
        for (int h = 0; h < 224; ++h) T += R[h];
        float head[11], tail[11];
        head[0] = 0.f; tail[0] = 0.f;
#pragma unroll
        for (int i = 1; i <= 10; ++i) { head[i] = head[i-1] + R[i-1]; tail[i] = tail[i-1] + R[224-i]; }
        float a0 = 0.f, a1 = 0.f;
#pragma unroll
        for (int t = 0; t < 21; ++t) {
            int d = t - 10;
            float clip = T - (d > 0 ? head[d] : tail[-d]);
            a0 += wl[t] * clip;
            a1 += ws[t] * clip;
        }
        vb[pass][e]     = a0 * (1.f / 50176.f);
        vb[2 + pass][e] = a1 * (1.f / 50176.f);
    }
    __syncthreads();
    int d = threadIdx.x;
    float contrib[4];
#pragma unroll
    for (int dir = 0; dir < 2; ++dir) {
        const float* row = g_G64 + dir * 32768 + b * 4096 + d * 64;
        float m = -1e30f;
        for (int j = 0; j < 64; ++j) m = fmaxf(m, row[j] * 0.125f);
        float s = 0.f, dot = 0.f;
        for (int j = 0; j < 64; ++j) {
            float w = __expf(row[j] * 0.125f - m);
            s += w;
            dot += w * vb[dir][j];
        }
        contrib[dir] = dot / s;
    }
#pragma unroll
    for (int dir = 0; dir < 2; ++dir) {
        const float* row = g_G8 + dir * 4096 + b * 512 + d * 8;
        int base = d & ~7;
        float m = -1e30f;
#pragma unroll
        for (int j = 0; j < 8; ++j) m = fmaxf(m, row[j] * 0.35355339059327373f);
        float s = 0.f, dot = 0.f;
#pragma unroll
        for (int j = 0; j < 8; ++j) {
            float w = __expf(row[j] * 0.35355339059327373f - m);
            s += w;
            dot += w * vb[2 + dir][base + j];
        }
        contrib[2 + dir] = dot / s;
    }
    float a = mix[0] * contrib[0] + mix[1] * contrib[1]
            + mix[2] * contrib[2] + mix[3] * contrib[3];
    g_S[b * 64 + d] = 1.f / (1.f + __expf(-a));
}

// -------- apply gate: out = sigmoid(a)[b,c] * x. grid (49, 512), block 256 --------
__global__ __launch_bounds__(256) void apply_kernel(const float* __restrict__ x,
                                                    float* __restrict__ out) {
    int bc = blockIdx.y;                       // 0..511 = b*64+c
    int i = blockIdx.x * blockDim.x + threadIdx.x;   // 0..12543 (float4 within plane)
    float s = g_S[bc];
    size_t off = (size_t)bc * (PLANE / 4) + i;
    float4 v = ((const float4*)x)[off];
    v.x *= s; v.y *= s; v.z *= s; v.w *= s;
    ((float4*)out)[off] = v;
}

extern "C" void kernel_launch(void* const* d_in, const int* in_sizes, int n_in,
                              void* d_out, int out_size) {
    const float* x      = (const float*)d_in[0];
    const float* lrb_qh = (const float*)d_in[1];
    const float* lrb_qw = (const float*)d_in[2];
    const float* lrb_kh = (const float*)d_in[3];
    const float* lrb_kw = (const float*)d_in[4];
    const float* lrb_vh = (const float*)d_in[5];
    const float* lrb_vw = (const float*)d_in[6];
    const float* srb_qh = (const float*)d_in[7];
    const float* srb_qw = (const float*)d_in[8];
    const float* srb_kh = (const float*)d_in[9];
    const float* srb_kw = (const float*)d_in[10];
    const float* srb_vh = (const float*)d_in[11];
    const float* srb_vw = (const float*)d_in[12];
    const float* mix_w  = (const float*)d_in[13];
    float* out = (float*)d_out;

    sums_kernel<<<dim3(64, 8), 224>>>(x);

    convh_kernel<<<dim3(49, 64, 8), 256>>>(x, lrb_qh, lrb_kh, srb_qh, srb_kh);
    gram64_kernel<<<dim3(NS, 8), 256>>>();
    gram8_kernel<<<dim3(NS, 8), 256>>>();
    reduce_kernel<<<144, 256>>>(0);

    convw_kernel<<<dim3(49, 64, 8), 256>>>(x, lrb_qw, lrb_kw, srb_qw, srb_kw);
    gram64_kernel<<<dim3(NS, 8), 256>>>();
    gram8_kernel<<<dim3(NS, 8), 256>>>();
    reduce_kernel<<<144, 256>>>(1);

    finalize_kernel<<<8, 64>>>(lrb_vh, lrb_vw, srb_vh, srb_vw, mix_w);
    apply_kernel<<<dim3(49, 512), 256>>>(x, out);
}

// round 6
// speedup vs baseline: 1.2286x; 1.0330x over previous
#include <cuda_runtime.h>
#include <cuda_bf16.h>
#include <cstdint>

#define BB 8
#define CC 64
#define PLANE 50176
#define CHW   (64*50176)
#define BCHW  (8*64*50176)
#define NS 112
#define KSLICE 448    // 50176 / 112  (gram64)
#define NS8 14
#define KSLICE8 3584  // 50176 / 14   (gram8)

// ---------------- scratch (static device globals; no runtime allocation) ----------------
__device__ __align__(16) __nv_bfloat16 g_Q[2ull * BCHW];   // [branch][b][c][n]
__device__ __align__(16) __nv_bfloat16 g_K[2ull * BCHW];
__device__ float g_P64[NS * 8 * 4096];     // [slice][b][64][64] lrb partial gram
__device__ float g_P8 [NS8 * 8 * 512];     // [slice][b][64][8]  srb partial gram
__device__ float g_G64[2 * 8 * 4096];      // [dir][b][64][64]
__device__ float g_G8 [2 * 8 * 512];       // [dir][b][64][8]
__device__ float g_R [8 * 64 * 224];       // row sums (over w)
__device__ float g_Cs[8 * 64 * 224];       // col sums (over h)
__device__ float g_S [8 * 64];             // sigmoid gates

static __device__ __forceinline__ void store4bf16(__nv_bfloat16* p, float a, float b,
                                                  float c, float d) {
    __nv_bfloat162 lo = __floats2bfloat162_rn(a, b);
    __nv_bfloat162 hi = __floats2bfloat162_rn(c, d);
    uint2 u;
    u.x = *reinterpret_cast<unsigned int*>(&lo);
    u.y = *reinterpret_cast<unsigned int*>(&hi);
    *reinterpret_cast<uint2*>(p) = u;
}

static __device__ __forceinline__ void unpack8(uint4 u, float* f) {
    float2 a;
    a = __bfloat1622float2(*(__nv_bfloat162*)&u.x); f[0] = a.x; f[1] = a.y;
    a = __bfloat1622float2(*(__nv_bfloat162*)&u.y); f[2] = a.x; f[3] = a.y;
    a = __bfloat1622float2(*(__nv_bfloat162*)&u.z); f[4] = a.x; f[5] = a.y;
    a = __bfloat1622float2(*(__nv_bfloat162*)&u.w); f[6] = a.x; f[7] = a.y;
}

// -------- row & column sums: grid (c=64, b=8), block 224 --------
__global__ __launch_bounds__(224) void sums_kernel(const float* __restrict__ x) {
    int c = blockIdx.x, b = blockIdx.y;
    int t = threadIdx.x, lane = t & 31, wp = t >> 5;
    const float* p = x + (size_t)(b * CC + c) * PLANE;
    __shared__ float part[224][8];
    float col = 0.f;
    for (int h = 0; h < 224; ++h) {
        float v = p[h * 224 + t];
        col += v;
        float r = v;
        r += __shfl_down_sync(0xffffffffu, r, 16);
        r += __shfl_down_sync(0xffffffffu, r, 8);
        r += __shfl_down_sync(0xffffffffu, r, 4);
        r += __shfl_down_sync(0xffffffffu, r, 2);
        r += __shfl_down_sync(0xffffffffu, r, 1);
        if (lane == 0) part[h][wp] = r;
    }
    __syncthreads();
    g_Cs[(size_t)(b * CC + c) * 224 + t] = col;
    float rs = 0.f;
#pragma unroll
    for (int w = 0; w < 7; ++w) rs += part[t][w];
    g_R[(size_t)(b * CC + c) * 224 + t] = rs;
}

// -------- conv along H for q(7) and k(11), both branches. grid (49, c, b), block 256 --------
__global__ __launch_bounds__(256) void convh_kernel(
        const float* __restrict__ x,
        const float* __restrict__ lq, const float* __restrict__ lk,
        const float* __restrict__ sq, const float* __restrict__ sk) {
    int c = blockIdx.y, b = blockIdx.z;
    int t = blockIdx.x * blockDim.x + threadIdx.x;   // 0..12543
    int h = t / 56;
    int w4 = (t % 56) * 4;
    float wql[7], wqs[7], wkl[11], wks[11];
#pragma unroll
    for (int i = 0; i < 7; ++i) { wql[i] = lq[c * 7 + i]; wqs[i] = sq[c * 7 + i]; }
#pragma unroll
    for (int i = 0; i < 11; ++i) { wkl[i] = lk[c * 11 + i]; wks[i] = sk[c * 11 + i]; }
    const float* xb = x + (size_t)(b * CC + c) * PLANE;
    float ql[4] = {0,0,0,0}, qs[4] = {0,0,0,0};
    float kl[4] = {0,0,0,0}, ks[4] = {0,0,0,0};
#pragma unroll
    for (int i = 0; i < 11; ++i) {
        int hh = h + i - 5;                       // k taps: offsets -5..5
        if (hh >= 0 && hh < 224) {
            float4 v = *(const float4*)(xb + hh * 224 + w4);
            float vv[4] = {v.x, v.y, v.z, v.w};
#pragma unroll
            for (int j = 0; j < 4; ++j) { kl[j] += wkl[i] * vv[j]; ks[j] += wks[i] * vv[j]; }
            if (i >= 2 && i <= 8) {               // q taps: offsets -3..3
#pragma unroll
                for (int j = 0; j < 4; ++j) { ql[j] += wql[i-2] * vv[j]; qs[j] += wqs[i-2] * vv[j]; }
            }
        }
    }
    size_t off = (size_t)(b * CC + c) * PLANE + h * 224 + w4;
    store4bf16(g_Q + off,        ql[0], ql[1], ql[2], ql[3]);
    store4bf16(g_Q + BCHW + off, qs[0], qs[1], qs[2], qs[3]);
    store4bf16(g_K + off,        kl[0], kl[1], kl[2], kl[3]);
    store4bf16(g_K + BCHW + off, ks[0], ks[1], ks[2], ks[3]);
}

// -------- conv along W. Same grid/block as convh --------
__global__ __launch_bounds__(256) void convw_kernel(
        const float* __restrict__ x,
        const float* __restrict__ lq, const float* __restrict__ lk,
        const float* __restrict__ sq, const float* __restrict__ sk) {
    int c = blockIdx.y, b = blockIdx.z;
    int t = blockIdx.x * blockDim.x + threadIdx.x;
    int h = t / 56;
    int w4 = (t % 56) * 4;
    float wql[7], wqs[7], wkl[11], wks[11];
#pragma unroll
    for (int i = 0; i < 7; ++i) { wql[i] = lq[c * 7 + i]; wqs[i] = sq[c * 7 + i]; }
#pragma unroll
    for (int i = 0; i < 11; ++i) { wkl[i] = lk[c * 11 + i]; wks[i] = sk[c * 11 + i]; }
    const float* xr = x + (size_t)(b * CC + c) * PLANE + h * 224;
    float buf[20];                                 // x columns [w4-8, w4+11]
#pragma unroll
    for (int i = 0; i < 20; ++i) buf[i] = 0.f;
#pragma unroll
    for (int s = 0; s < 5; ++s) {
        int wb = w4 - 8 + s * 4;
        if (wb >= 0 && wb < 224) {
            float4 v = *(const float4*)(xr + wb);
            buf[s*4+0] = v.x; buf[s*4+1] = v.y; buf[s*4+2] = v.z; buf[s*4+3] = v.w;
        }
    }
    float ql[4], qs[4], kl[4], ks[4];
#pragma unroll
    for (int j = 0; j < 4; ++j) {
        float aql = 0, aqs = 0, akl = 0, aks = 0;
#pragma unroll
        for (int i = 0; i < 11; ++i) { float v = buf[j+i+3]; akl += wkl[i]*v; aks += wks[i]*v; }
#pragma unroll
        for (int i = 0; i < 7; ++i)  { float v = buf[j+i+5]; aql += wql[i]*v; aqs += wqs[i]*v; }
        ql[j] = aql; qs[j] = aqs; kl[j] = akl; ks[j] = aks;
    }
    size_t off = (size_t)(b * CC + c) * PLANE + h * 224 + w4;
    store4bf16(g_Q + off,        ql[0], ql[1], ql[2], ql[3]);
    store4bf16(g_Q + BCHW + off, qs[0], qs[1], qs[2], qs[3]);
    store4bf16(g_K + off,        kl[0], kl[1], kl[2], kl[3]);
    store4bf16(g_K + BCHW + off, ks[0], ks[1], ks[2], ks[3]);
}

// -------- lrb full 64x64 Gram over a K-slice. grid (NS, b=8), block 256 --------
__global__ __launch_bounds__(256) void gram64_kernel() {
    int slice = blockIdx.x, b = blockIdx.y;
    const __nv_bfloat16* Qb = g_Q + (size_t)b * CHW;
    const __nv_bfloat16* Kb = g_K + (size_t)b * CHW;
    __shared__ __align__(16) float Qs[32][68];
    __shared__ __align__(16) float Ksm[32][68];
    int t = threadIdx.x;
    int lc = t >> 2, n8 = (t & 3) * 8;
    int tx = t & 15, ty = t >> 4;
    float acc[4][4] = {};
    int n0 = slice * KSLICE;
    for (int kk = 0; kk < KSLICE; kk += 32) {
        uint4 uq = *(const uint4*)(Qb + (size_t)lc * PLANE + n0 + kk + n8);
        uint4 uk = *(const uint4*)(Kb + (size_t)lc * PLANE + n0 + kk + n8);
        __syncthreads();
        float f[8];
        unpack8(uq, f);
#pragma unroll
        for (int i = 0; i < 8; ++i) Qs[n8 + i][lc] = f[i];
        unpack8(uk, f);
#pragma unroll
        for (int i = 0; i < 8; ++i) Ksm[n8 + i][lc] = f[i];
        __syncthreads();
#pragma unroll
        for (int ks = 0; ks < 32; ++ks) {
            float4 a  = *(const float4*)&Qs[ks][ty * 4];
            float4 bv = *(const float4*)&Ksm[ks][tx * 4];
            float av[4] = {a.x, a.y, a.z, a.w};
            float bw[4] = {bv.x, bv.y, bv.z, bv.w};
#pragma unroll
            for (int i = 0; i < 4; ++i)
#pragma unroll
                for (int j = 0; j < 4; ++j) acc[i][j] += av[i] * bw[j];
        }
    }
    float* out = g_P64 + ((size_t)slice * 8 + b) * 4096;
#pragma unroll
    for (int i = 0; i < 4; ++i)
#pragma unroll
        for (int j = 0; j < 4; ++j)
            out[(ty * 4 + i) * 64 + tx * 4 + j] = acc[i][j];
}

// -------- srb per-head Gram, channel-major smem, n-vectorized --------
// grid (NS8, head=8, b=8), block 256. smem [16 rows (8q|8k)][512+4 pad].
#define TN 512
#define ROWP (TN + 4)
__global__ __launch_bounds__(256) void gram8_kernel() {
    int slice = blockIdx.x, h = blockIdx.y, b = blockIdx.z;
    const __nv_bfloat16* Qb = g_Q + BCHW + (size_t)(b * CC + h * 8) * PLANE;
    const __nv_bfloat16* Kb = g_K + BCHW + (size_t)(b * CC + h * 8) * PLANE;
    __shared__ __align__(16) float sm[16 * ROWP];
    int t = threadIdx.x;
    int role = t & 3, nsplit = t >> 2;
    int qi = role >> 1, qj = role & 1;          // quadrant halves
    float acc[4][4] = {};
    int n0 = slice * KSLICE8;
    for (int chunk = 0; chunk < KSLICE8 / TN; ++chunk) {
        int nb = n0 + chunk * TN;
        __syncthreads();
#pragma unroll
        for (int u = t; u < 1024; u += 256) {
            int row = u >> 6;                   // 0..15
            int off = (u & 63) * 8;             // 0..504
            const __nv_bfloat16* src = (row < 8 ? Qb + (size_t)row * PLANE
                                                : Kb + (size_t)(row - 8) * PLANE) + nb + off;
            uint4 v = *(const uint4*)src;
            float f[8];
            unpack8(v, f);
            float* dst = sm + row * ROWP + off;
            *(float4*)(dst)     = make_float4(f[0], f[1], f[2], f[3]);
            *(float4*)(dst + 4) = make_float4(f[4], f[5], f[6], f[7]);
        }
        __syncthreads();
#pragma unroll
        for (int step = 0; step < 2; ++step) {
            int n4 = nsplit * 8 + step * 4;
            float4 qf[4], kf[4];
#pragma unroll
            for (int i = 0; i < 4; ++i)
                qf[i] = *(const float4*)(sm + (qi * 4 + i) * ROWP + n4);
#pragma unroll
            for (int j = 0; j < 4; ++j)
                kf[j] = *(const float4*)(sm + (8 + qj * 4 + j) * ROWP + n4);
#pragma unroll
            for (int i = 0; i < 4; ++i)
#pragma unroll
                for (int j = 0; j < 4; ++j) {
                    acc[i][j] += qf[i].x * kf[j].x + qf[i].y * kf[j].y
                               + qf[i].z * kf[j].z + qf[i].w * kf[j].w;
                }
        }
    }
    // reduce over nsplit within warp (lane bits 2..4)
#pragma unroll
    for (int i = 0; i < 4; ++i)
#pragma unroll
        for (int j = 0; j < 4; ++j) {
            float v = acc[i][j];
            v += __shfl_xor_sync(0xffffffffu, v, 4);
            v += __shfl_xor_sync(0xffffffffu, v, 8);
            v += __shfl_xor_sync(0xffffffffu, v, 16);
            acc[i][j] = v;
        }
    __syncthreads();                    // smem reads done; reuse as red buffer
    float* red = sm;                    // [warp*4 + role][16]
    int lane = t & 31, w = t >> 5;
    if (lane < 4) {
#pragma unroll
        for (int i = 0; i < 4; ++i)
#pragma unroll
            for (int j = 0; j < 4; ++j)
                red[(w * 4 + lane) * 16 + i * 4 + j] = acc[i][j];
    }
    __syncthreads();
    if (t < 64) {
        int di = t >> 3, ej = t & 7;
        int rr = (di >> 2) * 2 + (ej >> 2);       // role
        int idx = (di & 3) * 4 + (ej & 3);
        float s = 0.f;
#pragma unroll
        for (int ww = 0; ww < 8; ++ww) s += red[(ww * 4 + rr) * 16 + idx];
        g_P8[(((size_t)slice * 8 + b) * 8 + h) * 64 + t] = s;
    }
}

// -------- reduce partial grams into g_G64/g_G8 for one direction --------
__global__ __launch_bounds__(256) void reduce_kernel(int dir) {
    int idx = blockIdx.x * blockDim.x + threadIdx.x;   // 0..36863
    if (idx < 32768) {
        float s = 0.f;
        for (int sl = 0; sl < NS; ++sl) s += g_P64[(size_t)sl * 32768 + idx];
        g_G64[dir * 32768 + idx] = s;
    } else {
        int j = idx - 32768;
        if (j < 4096) {
            float s = 0.f;
            for (int sl = 0; sl < NS8; ++sl) s += g_P8[(size_t)sl * 4096 + j];
            g_G8[dir * 4096 + j] = s;
        }
    }
}

// -------- finalize: vbar + softmax + mix + sigmoid. grid 8 (b), block 64 --------
__global__ __launch_bounds__(64) void finalize_kernel(
        const float* __restrict__ lvh, const float* __restrict__ lvw,
        const float* __restrict__ svh, const float* __restrict__ svw,
        const float* __restrict__ mix) {
    int b = blockIdx.x;
    int e = threadIdx.x;
    __shared__ float vb[4][64];   // 0:lrb_h 1:lrb_w 2:srb_h 3:srb_w
    for (int pass = 0; pass < 2; ++pass) {
        const float* R = (pass == 0 ? g_R : g_Cs) + (size_t)(b * 64 + e) * 224;
        const float* wl = (pass == 0 ? lvh : lvw) + e * 21;
        const float* ws = (pass == 0 ? svh : svw) + e * 21;
        float T = 0.f;
        for (int h = 0; h < 224; ++h) T += R[h];
        float head[11], tail[11];
        head[0] = 0.f; tail[0] = 0.f;
#pragma unroll
        for (int i = 1; i <= 10; ++i) { head[i] = head[i-1] + R[i-1]; tail[i] = tail[i-1] + R[224-i]; }
        float a0 = 0.f, a1 = 0.f;
#pragma unroll
        for (int t = 0; t < 21; ++t) {
            int d = t - 10;
            float clip = T - (d > 0 ? head[d] : tail[-d]);
            a0 += wl[t] * clip;
            a1 += ws[t] * clip;
        }
        vb[pass][e]     = a0 * (1.f / 50176.f);
        vb[2 + pass][e] = a1 * (1.f / 50176.f);
    }
    __syncthreads();
    int d = threadIdx.x;
    float contrib[4];
#pragma unroll
    for (int dir = 0; dir < 2; ++dir) {
        const float* row = g_G64 + dir * 32768 + b * 4096 + d * 64;
        float m = -1e30f;
        for (int j = 0; j < 64; ++j) m = fmaxf(m, row[j] * 0.125f);
        float s = 0.f, dot = 0.f;
        for (int j = 0; j < 64; ++j) {
            float w = __expf(row[j] * 0.125f - m);
            s += w;
            dot += w * vb[dir][j];
        }
        contrib[dir] = dot / s;
    }
#pragma unroll
    for (int dir = 0; dir < 2; ++dir) {
        const float* row = g_G8 + dir * 4096 + b * 512 + d * 8;
        int base = d & ~7;
        float m = -1e30f;
#pragma unroll
        for (int j = 0; j < 8; ++j) m = fmaxf(m, row[j] * 0.35355339059327373f);
        float s = 0.f, dot = 0.f;
#pragma unroll
        for (int j = 0; j < 8; ++j) {
            float w = __expf(row[j] * 0.35355339059327373f - m);
            s += w;
            dot += w * vb[2 + dir][base + j];
        }
        contrib[2 + dir] = dot / s;
    }
    float a = mix[0] * contrib[0] + mix[1] * contrib[1]
            + mix[2] * contrib[2] + mix[3] * contrib[3];
    g_S[b * 64 + d] = 1.f / (1.f + __expf(-a));
}

// -------- apply gate: out = sigmoid(a)[b,c] * x. grid (49, 512), block 256 --------
__global__ __launch_bounds__(256) void apply_kernel(const float* __restrict__ x,
                                                    float* __restrict__ out) {
    int bc = blockIdx.y;                       // 0..511 = b*64+c
    int i = blockIdx.x * blockDim.x + threadIdx.x;   // 0..12543 (float4 within plane)
    float s = g_S[bc];
    size_t off = (size_t)bc * (PLANE / 4) + i;
    float4 v = ((const float4*)x)[off];
    v.x *= s; v.y *= s; v.z *= s; v.w *= s;
    ((float4*)out)[off] = v;
}

extern "C" void kernel_launch(void* const* d_in, const int* in_sizes, int n_in,
                              void* d_out, int out_size) {
    const float* x      = (const float*)d_in[0];
    const float* lrb_qh = (const float*)d_in[1];
    const float* lrb_qw = (const float*)d_in[2];
    const float* lrb_kh = (const float*)d_in[3];
    const float* lrb_kw = (const float*)d_in[4];
    const float* lrb_vh = (const float*)d_in[5];
    const float* lrb_vw = (const float*)d_in[6];
    const float* srb_qh = (const float*)d_in[7];
    const float* srb_qw = (const float*)d_in[8];
    const float* srb_kh = (const float*)d_in[9];
    const float* srb_kw = (const float*)d_in[10];
    const float* srb_vh = (const float*)d_in[11];
    const float* srb_vw = (const float*)d_in[12];
    const float* mix_w  = (const float*)d_in[13];
    float* out = (float*)d_out;

    sums_kernel<<<dim3(64, 8), 224>>>(x);

    convh_kernel<<<dim3(49, 64, 8), 256>>>(x, lrb_qh, lrb_kh, srb_qh, srb_kh);
    gram64_kernel<<<dim3(NS, 8), 256>>>();
    gram8_kernel<<<dim3(NS8, 8, 8), 256>>>();
    reduce_kernel<<<144, 256>>>(0);

    convw_kernel<<<dim3(49, 64, 8), 256>>>(x, lrb_qw, lrb_kw, srb_qw, srb_kw);
    gram64_kernel<<<dim3(NS, 8), 256>>>();
    gram8_kernel<<<dim3(NS8, 8, 8), 256>>>();
    reduce_kernel<<<144, 256>>>(1);

    finalize_kernel<<<8, 64>>>(lrb_vh, lrb_vw, srb_vh, srb_vw, mix_w);
    apply_kernel<<<dim3(49, 512), 256>>>(x, out);
}

// round 8
// speedup vs baseline: 1.7645x; 1.4362x over previous
#include <cuda_runtime.h>
#include <cuda_bf16.h>
#include <cstdint>

#define BB 8
#define CC 64
#define PLANE 50176
#define CHW   (64*50176)
#define BCHW  (8*64*50176)
#define NSG 28
#define KSG 1792     // 50176 / 28

// ---------------- scratch (static device globals; no runtime allocation) ----------------
__device__ __align__(16) __nv_bfloat16 g_Q[2ull * BCHW];   // [branch][b][c][n]
__device__ __align__(16) __nv_bfloat16 g_K[2ull * BCHW];
__device__ float g_P  [2 * NSG * 8 * 4096];  // [branch][slice][b][64][64] partial grams
__device__ float g_G64[2 * 8 * 4096];        // [dir][b][64][64]
__device__ float g_G8 [2 * 8 * 512];         // [dir][b][64][8]
__device__ float g_R [8 * 64 * 224];         // row sums (over w)
__device__ float g_Cs[8 * 64 * 224];         // col sums (over h)
__device__ float g_S [8 * 64];               // sigmoid gates

static __device__ __forceinline__ void store4bf16(__nv_bfloat16* p, float a, float b,
                                                  float c, float d) {
    __nv_bfloat162 lo = __floats2bfloat162_rn(a, b);
    __nv_bfloat162 hi = __floats2bfloat162_rn(c, d);
    uint2 u;
    u.x = *reinterpret_cast<unsigned int*>(&lo);
    u.y = *reinterpret_cast<unsigned int*>(&hi);
    *reinterpret_cast<uint2*>(p) = u;
}

static __device__ __forceinline__ uint32_t smem_u32(const void* p) {
    return (uint32_t)__cvta_generic_to_shared(p);
}

// -------- row & column sums: grid (c=64, b=8), block 224 --------
__global__ __launch_bounds__(224) void sums_kernel(const float* __restrict__ x) {
    int c = blockIdx.x, b = blockIdx.y;
    int t = threadIdx.x, lane = t & 31, wp = t >> 5;
    const float* p = x + (size_t)(b * CC + c) * PLANE;
    __shared__ float part[224][8];
    float col = 0.f;
    for (int h = 0; h < 224; ++h) {
        float v = p[h * 224 + t];
        col += v;
        float r = v;
        r += __shfl_down_sync(0xffffffffu, r, 16);
        r += __shfl_down_sync(0xffffffffu, r, 8);
        r += __shfl_down_sync(0xffffffffu, r, 4);
        r += __shfl_down_sync(0xffffffffu, r, 2);
        r += __shfl_down_sync(0xffffffffu, r, 1);
        if (lane == 0) part[h][wp] = r;
    }
    __syncthreads();
    g_Cs[(size_t)(b * CC + c) * 224 + t] = col;
    float rs = 0.f;
#pragma unroll
    for (int w = 0; w < 7; ++w) rs += part[t][w];
    g_R[(size_t)(b * CC + c) * 224 + t] = rs;
}

// -------- conv along H for q(7) and k(11), both branches. grid (49, c, b), block 256 --------
__global__ __launch_bounds__(256) void convh_kernel(
        const float* __restrict__ x,
        const float* __restrict__ lq, const float* __restrict__ lk,
        const float* __restrict__ sq, const float* __restrict__ sk) {
    int c = blockIdx.y, b = blockIdx.z;
    int t = blockIdx.x * blockDim.x + threadIdx.x;   // 0..12543
    int h = t / 56;
    int w4 = (t % 56) * 4;
    float wql[7], wqs[7], wkl[11], wks[11];
#pragma unroll
    for (int i = 0; i < 7; ++i) { wql[i] = lq[c * 7 + i]; wqs[i] = sq[c * 7 + i]; }
#pragma unroll
    for (int i = 0; i < 11; ++i) { wkl[i] = lk[c * 11 + i]; wks[i] = sk[c * 11 + i]; }
    const float* xb = x + (size_t)(b * CC + c) * PLANE;
    float ql[4] = {0,0,0,0}, qs[4] = {0,0,0,0};
    float kl[4] = {0,0,0,0}, ks[4] = {0,0,0,0};
#pragma unroll
    for (int i = 0; i < 11; ++i) {
        int hh = h + i - 5;                       // k taps: offsets -5..5
        if (hh >= 0 && hh < 224) {
            float4 v = *(const float4*)(xb + hh * 224 + w4);
            float vv[4] = {v.x, v.y, v.z, v.w};
#pragma unroll
            for (int j = 0; j < 4; ++j) { kl[j] += wkl[i] * vv[j]; ks[j] += wks[i] * vv[j]; }
            if (i >= 2 && i <= 8) {               // q taps: offsets -3..3
#pragma unroll
                for (int j = 0; j < 4; ++j) { ql[j] += wql[i-2] * vv[j]; qs[j] += wqs[i-2] * vv[j]; }
            }
        }
    }
    size_t off = (size_t)(b * CC + c) * PLANE + h * 224 + w4;
    store4bf16(g_Q + off,        ql[0], ql[1], ql[2], ql[3]);
    store4bf16(g_Q + BCHW + off, qs[0], qs[1], qs[2], qs[3]);
    store4bf16(g_K + off,        kl[0], kl[1], kl[2], kl[3]);
    store4bf16(g_K + BCHW + off, ks[0], ks[1], ks[2], ks[3]);
}

// -------- conv along W. Same grid/block as convh --------
__global__ __launch_bounds__(256) void convw_kernel(
        const float* __restrict__ x,
        const float* __restrict__ lq, const float* __restrict__ lk,
        const float* __restrict__ sq, const float* __restrict__ sk) {
    int c = blockIdx.y, b = blockIdx.z;
    int t = blockIdx.x * blockDim.x + threadIdx.x;
    int h = t / 56;
    int w4 = (t % 56) * 4;
    float wql[7], wqs[7], wkl[11], wks[11];
#pragma unroll
    for (int i = 0; i < 7; ++i) { wql[i] = lq[c * 7 + i]; wqs[i] = sq[c * 7 + i]; }
#pragma unroll
    for (int i = 0; i < 11; ++i) { wkl[i] = lk[c * 11 + i]; wks[i] = sk[c * 11 + i]; }
    const float* xr = x + (size_t)(b * CC + c) * PLANE + h * 224;
    float buf[20];                                 // x columns [w4-8, w4+11]
#pragma unroll
    for (int i = 0; i < 20; ++i) buf[i] = 0.f;
#pragma unroll
    for (int s = 0; s < 5; ++s) {
        int wb = w4 - 8 + s * 4;
        if (wb >= 0 && wb < 224) {
            float4 v = *(const float4*)(xr + wb);
            buf[s*4+0] = v.x; buf[s*4+1] = v.y; buf[s*4+2] = v.z; buf[s*4+3] = v.w;
        }
    }
    float ql[4], qs[4], kl[4], ks[4];
#pragma unroll
    for (int j = 0; j < 4; ++j) {
        float aql = 0, aqs = 0, akl = 0, aks = 0;
#pragma unroll
        for (int i = 0; i < 11; ++i) { float v = buf[j+i+3]; akl += wkl[i]*v; aks += wks[i]*v; }
#pragma unroll
        for (int i = 0; i < 7; ++i)  { float v = buf[j+i+5]; aql += wql[i]*v; aqs += wqs[i]*v; }
        ql[j] = aql; qs[j] = aqs; kl[j] = akl; ks[j] = aks;
    }
    size_t off = (size_t)(b * CC + c) * PLANE + h * 224 + w4;
    store4bf16(g_Q + off,        ql[0], ql[1], ql[2], ql[3]);
    store4bf16(g_Q + BCHW + off, qs[0], qs[1], qs[2], qs[3]);
    store4bf16(g_K + off,        kl[0], kl[1], kl[2], kl[3]);
    store4bf16(g_K + BCHW + off, ks[0], ks[1], ks[2], ks[3]);
}

// -------- tensor-core Gram: G = Q[64,N] @ K[64,N]^T per (branch, b, slice) --------
// grid (NSG, b=8, branch=2), block 256 = 8 warps.
// warp w: m-slab (w&3)*16, n-half (w>>2)*32 (4 n-tiles of 8).
__global__ __launch_bounds__(256) void gram_mma_kernel() {
    int slice = blockIdx.x, b = blockIdx.y, br = blockIdx.z;
    const __nv_bfloat16* Qb = g_Q + (size_t)br * BCHW + (size_t)b * CHW;
    const __nv_bfloat16* Kb = g_K + (size_t)br * BCHW + (size_t)b * CHW;
    __shared__ __align__(16) __nv_bfloat16 Qs[64][72];   // 72 = 64 + 8 pad (conflict-free)
    __shared__ __align__(16) __nv_bfloat16 Ks[64][72];
    int t = threadIdx.x;
    int warp = t >> 5, lane = t & 31;
    int wm = (warp & 3) * 16;
    int wn = (warp >> 2) * 32;
    int lr = t >> 2;                 // load row 0..63
    int lo = (t & 3) * 8;            // load bf16 offset {0,8,16,24}
    float acc[4][4] = {};            // [n-tile][c0..c3]
    int n0 = slice * KSG;
    for (int kk = 0; kk < KSG; kk += 64) {
        const __nv_bfloat16* qsrc = Qb + (size_t)lr * PLANE + n0 + kk + lo;
        const __nv_bfloat16* ksrc = Kb + (size_t)lr * PLANE + n0 + kk + lo;
        uint4 q0 = *(const uint4*)qsrc;
        uint4 q1 = *(const uint4*)(qsrc + 32);
        uint4 k0 = *(const uint4*)ksrc;
        uint4 k1 = *(const uint4*)(ksrc + 32);
        __syncthreads();
        *(uint4*)&Qs[lr][lo]      = q0;
        *(uint4*)&Qs[lr][lo + 32] = q1;
        *(uint4*)&Ks[lr][lo]      = k0;
        *(uint4*)&Ks[lr][lo + 32] = k1;
        __syncthreads();
#pragma unroll
        for (int ks = 0; ks < 4; ++ks) {
            uint32_t a0, a1, a2, a3;
            uint32_t aaddr = smem_u32(&Qs[wm + (lane & 15)][((lane >> 4) & 1) * 8 + ks * 16]);
            asm volatile("ldmatrix.sync.aligned.m8n8.x4.shared.b16 {%0,%1,%2,%3}, [%4];"
                         : "=r"(a0), "=r"(a1), "=r"(a2), "=r"(a3) : "r"(aaddr));
#pragma unroll
            for (int nt = 0; nt < 4; ++nt) {
                uint32_t b0, b1;
                uint32_t baddr = smem_u32(&Ks[wn + nt * 8 + (lane & 7)][((lane >> 3) & 1) * 8 + ks * 16]);
                asm volatile("ldmatrix.sync.aligned.m8n8.x2.shared.b16 {%0,%1}, [%2];"
                             : "=r"(b0), "=r"(b1) : "r"(baddr));
                asm volatile("mma.sync.aligned.m16n8k16.row.col.f32.bf16.bf16.f32 "
                             "{%0,%1,%2,%3}, {%4,%5,%6,%7}, {%8,%9}, {%0,%1,%2,%3};"
                             : "+f"(acc[nt][0]), "+f"(acc[nt][1]), "+f"(acc[nt][2]), "+f"(acc[nt][3])
                             : "r"(a0), "r"(a1), "r"(a2), "r"(a3), "r"(b0), "r"(b1));
            }
        }
    }
    float* out = g_P + (((size_t)br * NSG + slice) * 8 + b) * 4096;
    int m0 = wm + (lane >> 2);
    int nn = (lane & 3) * 2;
#pragma unroll
    for (int nt = 0; nt < 4; ++nt) {
        int col = wn + nt * 8 + nn;
        out[m0 * 64 + col]           = acc[nt][0];
        out[m0 * 64 + col + 1]       = acc[nt][1];
        out[(m0 + 8) * 64 + col]     = acc[nt][2];
        out[(m0 + 8) * 64 + col + 1] = acc[nt][3];
    }
}

// -------- reduce partial grams: G64 from branch 0, G8 (block-diag) from branch 1 --------
__global__ __launch_bounds__(256) void reduce_kernel(int dir) {
    int idx = blockIdx.x * blockDim.x + threadIdx.x;   // 0..36863
    if (idx < 32768) {
        float s = 0.f;
        for (int sl = 0; sl < NSG; ++sl)
            s += g_P[((size_t)sl * 8) * 4096 + idx];          // branch 0
        g_G64[dir * 32768 + idx] = s;
    } else {
        int j = idx - 32768;
        if (j < 4096) {                                       // [b][d][e]
            int b = j >> 9, d = (j >> 3) & 63, e = j & 7;
            int col = (d & ~7) | e;
            float s = 0.f;
            for (int sl = 0; sl < NSG; ++sl)
                s += g_P[(((size_t)NSG + sl) * 8 + b) * 4096 + d * 64 + col];  // branch 1
            g_G8[dir * 4096 + j] = s;
        }
    }
}

// -------- finalize: vbar + softmax + mix + sigmoid. grid 8 (b), block 64 --------
__global__ __launch_bounds__(64) void finalize_kernel(
        const float* __restrict__ lvh, const float* __restrict__ lvw,
        const float* __restrict__ svh, const float* __restrict__ svw,
        const float* __restrict__ mix) {
    int b = blockIdx.x;
    int e = threadIdx.x;
    __shared__ float vb[4][64];   // 0:lrb_h 1:lrb_w 2:srb_h 3:srb_w
    for (int pass = 0; pass < 2; ++pass) {
        const float* R = (pass == 0 ? g_R : g_Cs) + (size_t)(b * 64 + e) * 224;
        const float* wl = (pass == 0 ? lvh : lvw) + e * 21;
        const float* ws = (pass == 0 ? svh : svw) + e * 21;
        float T = 0.f;
        for (int h = 0; h < 224; ++h) T += R[h];
        float head[11], tail[11];
        head[0] = 0.f; tail[0] = 0.f;
#pragma unroll
        for (int i = 1; i <= 10; ++i) { head[i] = head[i-1] + R[i-1]; tail[i] = tail[i-1] + R[224-i]; }
        float a0 = 0.f, a1 = 0.f;
#pragma unroll
        for (int t = 0; t < 21; ++t) {
            int d = t - 10;
            float clip = T - (d > 0 ? head[d] : tail[-d]);
            a0 += wl[t] * clip;
            a1 += ws[t] * clip;
        }
        vb[pass][e]     = a0 * (1.f / 50176.f);
        vb[2 + pass][e] = a1 * (1.f / 50176.f);
    }
    __syncthreads();
    int d = threadIdx.x;
    float contrib[4];
#pragma unroll
    for (int dir = 0; dir < 2; ++dir) {
        const float* row = g_G64 + dir * 32768 + b * 4096 + d * 64;
        float m = -1e30f;
        for (int j = 0; j < 64; ++j) m = fmaxf(m, row[j] * 0.125f);
        float s = 0.f, dot = 0.f;
        for (int j = 0; j < 64; ++j) {
            float w = __expf(row[j] * 0.125f - m);
            s += w;
            dot += w * vb[dir][j];
        }
        contrib[dir] = dot / s;
    }
#pragma unroll
    for (int dir = 0; dir < 2; ++dir) {
        const float* row = g_G8 + dir * 4096 + b * 512 + d * 8;
        int base = d & ~7;
        float m = -1e30f;
#pragma unroll
        for (int j = 0; j < 8; ++j) m = fmaxf(m, row[j] * 0.35355339059327373f);
        float s = 0.f, dot = 0.f;
#pragma unroll
        for (int j = 0; j < 8; ++j) {
            float w = __expf(row[j] * 0.35355339059327373f - m);
            s += w;
            dot += w * vb[2 + dir][base + j];
        }
        contrib[2 + dir] = dot / s;
    }
    float a = mix[0] * contrib[0] + mix[1] * contrib[1]
            + mix[2] * contrib[2] + mix[3] * contrib[3];
    g_S[b * 64 + d] = 1.f / (1.f + __expf(-a));
}

// -------- apply gate: out = sigmoid(a)[b,c] * x. grid (49, 512), block 256 --------
__global__ __launch_bounds__(256) void apply_kernel(const float* __restrict__ x,
                                                    float* __restrict__ out) {
    int bc = blockIdx.y;                       // 0..511 = b*64+c
    int i = blockIdx.x * blockDim.x + threadIdx.x;   // 0..12543 (float4 within plane)
    float s = g_S[bc];
    size_t off = (size_t)bc * (PLANE / 4) + i;
    float4 v = ((const float4*)x)[off];
    v.x *= s; v.y *= s; v.z *= s; v.w *= s;
    ((float4*)out)[off] = v;
}

extern "C" void kernel_launch(void* const* d_in, const int* in_sizes, int n_in,
                              void* d_out, int out_size) {
    const float* x      = (const float*)d_in[0];
    const float* lrb_qh = (const float*)d_in[1];
    const float* lrb_qw = (const float*)d_in[2];
    const float* lrb_kh = (const float*)d_in[3];
    const float* lrb_kw = (const float*)d_in[4];
    const float* lrb_vh = (const float*)d_in[5];
    const float* lrb_vw = (const float*)d_in[6];
    const float* srb_qh = (const float*)d_in[7];
    const float* srb_qw = (const float*)d_in[8];
    const float* srb_kh = (const float*)d_in[9];
    const float* srb_kw = (const float*)d_in[10];
    const float* srb_vh = (const float*)d_in[11];
    const float* srb_vw = (const float*)d_in[12];
    const float* mix_w  = (const float*)d_in[13];
    float* out = (float*)d_out;

    sums_kernel<<<dim3(64, 8), 224>>>(x);

    convh_kernel<<<dim3(49, 64, 8), 256>>>(x, lrb_qh, lrb_kh, srb_qh, srb_kh);
    gram_mma_kernel<<<dim3(NSG, 8, 2), 256>>>();
    reduce_kernel<<<144, 256>>>(0);

    convw_kernel<<<dim3(49, 64, 8), 256>>>(x, lrb_qw, lrb_kw, srb_qw, srb_kw);
    gram_mma_kernel<<<dim3(NSG, 8, 2), 256>>>();
    reduce_kernel<<<144, 256>>>(1);

    finalize_kernel<<<8, 64>>>(lrb_vh, lrb_vw, srb_vh, srb_vw, mix_w);
    apply_kernel<<<dim3(49, 512), 256>>>(x, out);
}

// round 11
// speedup vs baseline: 1.7701x; 1.0032x over previous
#include <cuda_runtime.h>
#include <cuda_bf16.h>
#include <cstdint>

#define BB 8
#define CC 64
#define PLANE 50176
#define CHW   (64*50176)
#define BCHW  (8*64*50176)
#define NSG 28
#define KSG 1792     // 50176 / 28
#define NCH (KSG / 64)

// ---------------- scratch (static device globals; no runtime allocation) ----------------
__device__ __align__(16) __nv_bfloat16 g_Q[2ull * BCHW];   // [branch][b][c][n]
__device__ __align__(16) __nv_bfloat16 g_K[2ull * BCHW];
__device__ float g_P  [2 * NSG * 8 * 4096];  // [branch][slice][b][64][64] partial grams
__device__ float g_G64[2 * 8 * 4096];        // [dir][b][64][64]
__device__ float g_G8 [2 * 8 * 512];         // [dir][b][64][8]
__device__ float g_R [8 * 64 * 224];         // row sums (over w)
__device__ float g_Cs[8 * 64 * 224];         // col sums (over h)
__device__ float g_S [8 * 64];               // sigmoid gates

static __device__ __forceinline__ void store4bf16(__nv_bfloat16* p, float a, float b,
                                                  float c, float d) {
    __nv_bfloat162 lo = __floats2bfloat162_rn(a, b);
    __nv_bfloat162 hi = __floats2bfloat162_rn(c, d);
    uint2 u;
    u.x = *reinterpret_cast<unsigned int*>(&lo);
    u.y = *reinterpret_cast<unsigned int*>(&hi);
    *reinterpret_cast<uint2*>(p) = u;
}

static __device__ __forceinline__ uint32_t smem_u32(const void* p) {
    return (uint32_t)__cvta_generic_to_shared(p);
}

// -------- row & column sums: grid (c=64, b=8), block 224 --------
__global__ __launch_bounds__(224) void sums_kernel(const float* __restrict__ x) {
    int c = blockIdx.x, b = blockIdx.y;
    int t = threadIdx.x, lane = t & 31, wp = t >> 5;
    const float* p = x + (size_t)(b * CC + c) * PLANE;
    __shared__ float part[224][8];
    float col = 0.f;
    for (int h = 0; h < 224; ++h) {
        float v = p[h * 224 + t];
        col += v;
        float r = v;
        r += __shfl_down_sync(0xffffffffu, r, 16);
        r += __shfl_down_sync(0xffffffffu, r, 8);
        r += __shfl_down_sync(0xffffffffu, r, 4);
        r += __shfl_down_sync(0xffffffffu, r, 2);
        r += __shfl_down_sync(0xffffffffu, r, 1);
        if (lane == 0) part[h][wp] = r;
    }
    __syncthreads();
    g_Cs[(size_t)(b * CC + c) * 224 + t] = col;
    float rs = 0.f;
#pragma unroll
    for (int w = 0; w < 7; ++w) rs += part[t][w];
    g_R[(size_t)(b * CC + c) * 224 + t] = rs;
}

// -------- conv along H for q(7) and k(11), both branches. grid (49, c, b), block 256 --------
__global__ __launch_bounds__(256) void convh_kernel(
        const float* __restrict__ x,
        const float* __restrict__ lq, const float* __restrict__ lk,
        const float* __restrict__ sq, const float* __restrict__ sk) {
    int c = blockIdx.y, b = blockIdx.z;
    int t = blockIdx.x * blockDim.x + threadIdx.x;   // 0..12543
    int h = t / 56;
    int w4 = (t % 56) * 4;
    float wql[7], wqs[7], wkl[11], wks[11];
#pragma unroll
    for (int i = 0; i < 7; ++i) { wql[i] = lq[c * 7 + i]; wqs[i] = sq[c * 7 + i]; }
#pragma unroll
    for (int i = 0; i < 11; ++i) { wkl[i] = lk[c * 11 + i]; wks[i] = sk[c * 11 + i]; }
    const float* xb = x + (size_t)(b * CC + c) * PLANE;
    float ql[4] = {0,0,0,0}, qs[4] = {0,0,0,0};
    float kl[4] = {0,0,0,0}, ks[4] = {0,0,0,0};
#pragma unroll
    for (int i = 0; i < 11; ++i) {
        int hh = h + i - 5;                       // k taps: offsets -5..5
        if (hh >= 0 && hh < 224) {
            float4 v = *(const float4*)(xb + hh * 224 + w4);
            float vv[4] = {v.x, v.y, v.z, v.w};
#pragma unroll
            for (int j = 0; j < 4; ++j) { kl[j] += wkl[i] * vv[j]; ks[j] += wks[i] * vv[j]; }
            if (i >= 2 && i <= 8) {               // q taps: offsets -3..3
#pragma unroll
                for (int j = 0; j < 4; ++j) { ql[j] += wql[i-2] * vv[j]; qs[j] += wqs[i-2] * vv[j]; }
            }
        }
    }
    size_t off = (size_t)(b * CC + c) * PLANE + h * 224 + w4;
    store4bf16(g_Q + off,        ql[0], ql[1], ql[2], ql[3]);
    store4bf16(g_Q + BCHW + off, qs[0], qs[1], qs[2], qs[3]);
    store4bf16(g_K + off,        kl[0], kl[1], kl[2], kl[3]);
    store4bf16(g_K + BCHW + off, ks[0], ks[1], ks[2], ks[3]);
}

// -------- conv along W. Same grid/block as convh --------
__global__ __launch_bounds__(256) void convw_kernel(
        const float* __restrict__ x,
        const float* __restrict__ lq, const float* __restrict__ lk,
        const float* __restrict__ sq, const float* __restrict__ sk) {
    int c = blockIdx.y, b = blockIdx.z;
    int t = blockIdx.x * blockDim.x + threadIdx.x;
    int h = t / 56;
    int w4 = (t % 56) * 4;
    float wql[7], wqs[7], wkl[11], wks[11];
#pragma unroll
    for (int i = 0; i < 7; ++i) { wql[i] = lq[c * 7 + i]; wqs[i] = sq[c * 7 + i]; }
#pragma unroll
    for (int i = 0; i < 11; ++i) { wkl[i] = lk[c * 11 + i]; wks[i] = sk[c * 11 + i]; }
    const float* xr = x + (size_t)(b * CC + c) * PLANE + h * 224;
    float buf[20];                                 // x columns [w4-8, w4+11]
#pragma unroll
    for (int i = 0; i < 20; ++i) buf[i] = 0.f;
#pragma unroll
    for (int s = 0; s < 5; ++s) {
        int wb = w4 - 8 + s * 4;
        if (wb >= 0 && wb < 224) {
            float4 v = *(const float4*)(xr + wb);
            buf[s*4+0] = v.x; buf[s*4+1] = v.y; buf[s*4+2] = v.z; buf[s*4+3] = v.w;
        }
    }
    float ql[4], qs[4], kl[4], ks[4];
#pragma unroll
    for (int j = 0; j < 4; ++j) {
        float aql = 0, aqs = 0, akl = 0, aks = 0;
#pragma unroll
        for (int i = 0; i < 11; ++i) { float v = buf[j+i+3]; akl += wkl[i]*v; aks += wks[i]*v; }
#pragma unroll
        for (int i = 0; i < 7; ++i)  { float v = buf[j+i+5]; aql += wql[i]*v; aqs += wqs[i]*v; }
        ql[j] = aql; qs[j] = aqs; kl[j] = akl; ks[j] = aks;
    }
    size_t off = (size_t)(b * CC + c) * PLANE + h * 224 + w4;
    store4bf16(g_Q + off,        ql[0], ql[1], ql[2], ql[3]);
    store4bf16(g_Q + BCHW + off, qs[0], qs[1], qs[2], qs[3]);
    store4bf16(g_K + off,        kl[0], kl[1], kl[2], kl[3]);
    store4bf16(g_K + BCHW + off, ks[0], ks[1], ks[2], ks[3]);
}

// -------- tensor-core Gram with register double-buffering --------
// grid (NSG, b=8, branch=2), block 256 = 8 warps. Single smem buffer;
// next chunk's LDGs are issued before the mma block so their latency is
// covered by compute + the trailing barrier.
__global__ __launch_bounds__(256) void gram_mma_kernel() {
    int slice = blockIdx.x, b = blockIdx.y, br = blockIdx.z;
    const __nv_bfloat16* Qb = g_Q + (size_t)br * BCHW + (size_t)b * CHW;
    const __nv_bfloat16* Kb = g_K + (size_t)br * BCHW + (size_t)b * CHW;
    __shared__ __align__(16) __nv_bfloat16 Qs[64][72];   // 72 = 64 + 8 pad
    __shared__ __align__(16) __nv_bfloat16 Ks[64][72];
    int t = threadIdx.x;
    int warp = t >> 5, lane = t & 31;
    int wm = (warp & 3) * 16;
    int wn = (warp >> 2) * 32;
    int lr = t >> 2;                 // load row 0..63
    int lo = (t & 3) * 8;            // load bf16 offset {0,8,16,24}
    float acc[4][4] = {};            // [n-tile][c0..c3]
    int n0 = slice * KSG;
    const __nv_bfloat16* qrow = Qb + (size_t)lr * PLANE + n0 + lo;
    const __nv_bfloat16* krow = Kb + (size_t)lr * PLANE + n0 + lo;

    // preload chunk 0 into registers
    uint4 q0 = *(const uint4*)qrow;
    uint4 q1 = *(const uint4*)(qrow + 32);
    uint4 k0 = *(const uint4*)krow;
    uint4 k1 = *(const uint4*)(krow + 32);

    for (int i = 0; i < NCH; ++i) {
        *(uint4*)&Qs[lr][lo]      = q0;
        *(uint4*)&Qs[lr][lo + 32] = q1;
        *(uint4*)&Ks[lr][lo]      = k0;
        *(uint4*)&Ks[lr][lo + 32] = k1;
        __syncthreads();
        if (i + 1 < NCH) {              // issue next chunk's loads now;
            int nb = (i + 1) * 64;      // latency hidden by the mma block below
            q0 = *(const uint4*)(qrow + nb);
            q1 = *(const uint4*)(qrow + nb + 32);
            k0 = *(const uint4*)(krow + nb);
            k1 = *(const uint4*)(krow + nb + 32);
        }
#pragma unroll
        for (int ks = 0; ks < 4; ++ks) {
            uint32_t a0, a1, a2, a3;
            uint32_t aaddr = smem_u32(&Qs[wm + (lane & 15)][((lane >> 4) & 1) * 8 + ks * 16]);
            asm volatile("ldmatrix.sync.aligned.m8n8.x4.shared.b16 {%0,%1,%2,%3}, [%4];"
                         : "=r"(a0), "=r"(a1), "=r"(a2), "=r"(a3) : "r"(aaddr));
#pragma unroll
            for (int nt = 0; nt < 4; ++nt) {
                uint32_t b0, b1;
                uint32_t baddr = smem_u32(&Ks[wn + nt * 8 + (lane & 7)][((lane >> 3) & 1) * 8 + ks * 16]);
                asm volatile("ldmatrix.sync.aligned.m8n8.x2.shared.b16 {%0,%1}, [%2];"
                             : "=r"(b0), "=r"(b1) : "r"(baddr));
                asm volatile("mma.sync.aligned.m16n8k16.row.col.f32.bf16.bf16.f32 "
                             "{%0,%1,%2,%3}, {%4,%5,%6,%7}, {%8,%9}, {%0,%1,%2,%3};"
                             : "+f"(acc[nt][0]), "+f"(acc[nt][1]), "+f"(acc[nt][2]), "+f"(acc[nt][3])
                             : "r"(a0), "r"(a1), "r"(a2), "r"(a3), "r"(b0), "r"(b1));
            }
        }
        __syncthreads();
    }
    float* out = g_P + (((size_t)br * NSG + slice) * 8 + b) * 4096;
    int m0 = wm + (lane >> 2);
    int nn = (lane & 3) * 2;
#pragma unroll
    for (int nt = 0; nt < 4; ++nt) {
        int col = wn + nt * 8 + nn;
        out[m0 * 64 + col]           = acc[nt][0];
        out[m0 * 64 + col + 1]       = acc[nt][1];
        out[(m0 + 8) * 64 + col]     = acc[nt][2];
        out[(m0 + 8) * 64 + col + 1] = acc[nt][3];
    }
}

// -------- reduce partial grams: G64 from branch 0, G8 (block-diag) from branch 1 --------
__global__ __launch_bounds__(256) void reduce_kernel(int dir) {
    int idx = blockIdx.x * blockDim.x + threadIdx.x;   // 0..36863
    if (idx < 32768) {
        float s = 0.f;
        for (int sl = 0; sl < NSG; ++sl)
            s += g_P[((size_t)sl * 8) * 4096 + idx];          // branch 0
        g_G64[dir * 32768 + idx] = s;
    } else {
        int j = idx - 32768;
        if (j < 4096) {                                       // [b][d][e]
            int b = j >> 9, d = (j >> 3) & 63, e = j & 7;
            int col = (d & ~7) | e;
            float s = 0.f;
            for (int sl = 0; sl < NSG; ++sl)
                s += g_P[(((size_t)NSG + sl) * 8 + b) * 4096 + d * 64 + col];  // branch 1
            g_G8[dir * 4096 + j] = s;
        }
    }
}

// -------- finalize: vbar + softmax + mix + sigmoid. grid 8 (b), block 64 --------
__global__ __launch_bounds__(64) void finalize_kernel(
        const float* __restrict__ lvh, const float* __restrict__ lvw,
        const float* __restrict__ svh, const float* __restrict__ svw,
        const float* __restrict__ mix) {
    int b = blockIdx.x;
    int e = threadIdx.x;
    __shared__ float vb[4][64];   // 0:lrb_h 1:lrb_w 2:srb_h 3:srb_w
    for (int pass = 0; pass < 2; ++pass) {
        const float* R = (pass == 0 ? g_R : g_Cs) + (size_t)(b * 64 + e) * 224;
        const float* wl = (pass == 0 ? lvh : lvw) + e * 21;
        const float* ws = (pass == 0 ? svh : svw) + e * 21;
        float T = 0.f;
        for (int h = 0; h < 224; ++h) T += R[h];
        float head[11], tail[11];
        head[0] = 0.f; tail[0] = 0.f;
#pragma unroll
        for (int i = 1; i <= 10; ++i) { head[i] = head[i-1] + R[i-1]; tail[i] = tail[i-1] + R[224-i]; }
        float a0 = 0.f, a1 = 0.f;
#pragma unroll
        for (int t = 0; t < 21; ++t) {
            int d = t - 10;
            float clip = T - (d > 0 ? head[d] : tail[-d]);
            a0 += wl[t] * clip;
            a1 += ws[t] * clip;
        }
        vb[pass][e]     = a0 * (1.f / 50176.f);
        vb[2 + pass][e] = a1 * (1.f / 50176.f);
    }
    __syncthreads();
    int d = threadIdx.x;
    float contrib[4];
#pragma unroll
    for (int dir = 0; dir < 2; ++dir) {
        const float* row = g_G64 + dir * 32768 + b * 4096 + d * 64;
        float m = -1e30f;
        for (int j = 0; j < 64; ++j) m = fmaxf(m, row[j] * 0.125f);
        float s = 0.f, dot = 0.f;
        for (int j = 0; j < 64; ++j) {
            float w = __expf(row[j] * 0.125f - m);
            s += w;
            dot += w * vb[dir][j];
        }
        contrib[dir] = dot / s;
    }
#pragma unroll
    for (int dir = 0; dir < 2; ++dir) {
        const float* row = g_G8 + dir * 4096 + b * 512 + d * 8;
        int base = d & ~7;
        float m = -1e30f;
#pragma unroll
        for (int j = 0; j < 8; ++j) m = fmaxf(m, row[j] * 0.35355339059327373f);
        float s = 0.f, dot = 0.f;
#pragma unroll
        for (int j = 0; j < 8; ++j) {
            float w = __expf(row[j] * 0.35355339059327373f - m);
            s += w;
            dot += w * vb[2 + dir][base + j];
        }
        contrib[2 + dir] = dot / s;
    }
    float a = mix[0] * contrib[0] + mix[1] * contrib[1]
            + mix[2] * contrib[2] + mix[3] * contrib[3];
    g_S[b * 64 + d] = 1.f / (1.f + __expf(-a));
}

// -------- apply gate: out = sigmoid(a)[b,c] * x. grid (49, 512), block 256 --------
__global__ __launch_bounds__(256) void apply_kernel(const float* __restrict__ x,
                                                    float* __restrict__ out) {
    int bc = blockIdx.y;                       // 0..511 = b*64+c
    int i = blockIdx.x * blockDim.x + threadIdx.x;   // 0..12543 (float4 within plane)
    float s = g_S[bc];
    size_t off = (size_t)bc * (PLANE / 4) + i;
    float4 v = ((const float4*)x)[off];
    v.x *= s; v.y *= s; v.z *= s; v.w *= s;
    ((float4*)out)[off] = v;
}

extern "C" void kernel_launch(void* const* d_in, const int* in_sizes, int n_in,
                              void* d_out, int out_size) {
    const float* x      = (const float*)d_in[0];
    const float* lrb_qh = (const float*)d_in[1];
    const float* lrb_qw = (const float*)d_in[2];
    const float* lrb_kh = (const float*)d_in[3];
    const float* lrb_kw = (const float*)d_in[4];
    const float* lrb_vh = (const float*)d_in[5];
    const float* lrb_vw = (const float*)d_in[6];
    const float* srb_qh = (const float*)d_in[7];
    const float* srb_qw = (const float*)d_in[8];
    const float* srb_kh = (const float*)d_in[9];
    const float* srb_kw = (const float*)d_in[10];
    const float* srb_vh = (const float*)d_in[11];
    const float* srb_vw = (const float*)d_in[12];
    const float* mix_w  = (const float*)d_in[13];
    float* out = (float*)d_out;

    sums_kernel<<<dim3(64, 8), 224>>>(x);

    convh_kernel<<<dim3(49, 64, 8), 256>>>(x, lrb_qh, lrb_kh, srb_qh, srb_kh);
    gram_mma_kernel<<<dim3(NSG, 8, 2), 256>>>();
    reduce_kernel<<<144, 256>>>(0);

    convw_kernel<<<dim3(49, 64, 8), 256>>>(x, lrb_qw, lrb_kw, srb_qw, srb_kw);
    gram_mma_kernel<<<dim3(NSG, 8, 2), 256>>>();
    reduce_kernel<<<144, 256>>>(1);

    finalize_kernel<<<8, 64>>>(lrb_vh, lrb_vw, srb_vh, srb_vw, mix_w);
    apply_kernel<<<dim3(49, 512), 256>>>(x, out);
}

// round 13
// speedup vs baseline: 2.0424x; 1.1538x over previous
#include <cuda_runtime.h>
#include <cuda_bf16.h>
#include <cstdint>

#define BB 8
#define CC 64
#define PLANE 50176
#define CHW   (64*50176)
#define BCHW  (8*64*50176)
#define NSG 28
#define KSG 1792     // 50176 / 28
#define NCH (KSG / 128)

// ---------------- scratch (static device globals; no runtime allocation) ----------------
__device__ __align__(16) uint8_t g_Q[2ull * BCHW];   // e4m3 [branch][b][c][n]
__device__ __align__(16) uint8_t g_K[2ull * BCHW];
__device__ float g_P  [2 * NSG * 8 * 4096];  // [branch][slice][b][64][64] partial grams
__device__ float g_G64[2 * 8 * 4096];        // [dir][b][64][64]
__device__ float g_G8 [2 * 8 * 512];         // [dir][b][64][8]
__device__ float g_R [8 * 64 * 224];         // row sums (over w)
__device__ float g_Cs[8 * 64 * 224];         // col sums (over h)
__device__ float g_S [8 * 64];               // sigmoid gates

static __device__ __forceinline__ uint32_t pack4fp8(float a, float b, float c, float d) {
    uint16_t lo, hi;   // cvt: first src -> upper byte, second -> lower byte
    asm("cvt.rn.satfinite.e4m3x2.f32 %0, %1, %2;" : "=h"(lo) : "f"(b), "f"(a));
    asm("cvt.rn.satfinite.e4m3x2.f32 %0, %1, %2;" : "=h"(hi) : "f"(d), "f"(c));
    return ((uint32_t)hi << 16) | lo;
}

static __device__ __forceinline__ uint32_t smem_u32(const void* p) {
    return (uint32_t)__cvta_generic_to_shared(p);
}

// -------- row & column sums: grid (c=64, b=8), block 224 --------
__global__ __launch_bounds__(224) void sums_kernel(const float* __restrict__ x) {
    int c = blockIdx.x, b = blockIdx.y;
    int t = threadIdx.x, lane = t & 31, wp = t >> 5;
    const float* p = x + (size_t)(b * CC + c) * PLANE;
    __shared__ float part[224][8];
    float col = 0.f;
    for (int h = 0; h < 224; ++h) {
        float v = p[h * 224 + t];
        col += v;
        float r = v;
        r += __shfl_down_sync(0xffffffffu, r, 16);
        r += __shfl_down_sync(0xffffffffu, r, 8);
        r += __shfl_down_sync(0xffffffffu, r, 4);
        r += __shfl_down_sync(0xffffffffu, r, 2);
        r += __shfl_down_sync(0xffffffffu, r, 1);
        if (lane == 0) part[h][wp] = r;
    }
    __syncthreads();
    g_Cs[(size_t)(b * CC + c) * 224 + t] = col;
    float rs = 0.f;
#pragma unroll
    for (int w = 0; w < 7; ++w) rs += part[t][w];
    g_R[(size_t)(b * CC + c) * 224 + t] = rs;
}

// -------- conv along H for q(7) and k(11), both branches. grid (49, c, b), block 256 --------
__global__ __launch_bounds__(256) void convh_kernel(
        const float* __restrict__ x,
        const float* __restrict__ lq, const float* __restrict__ lk,
        const float* __restrict__ sq, const float* __restrict__ sk) {
    int c = blockIdx.y, b = blockIdx.z;
    int t = blockIdx.x * blockDim.x + threadIdx.x;   // 0..12543
    int h = t / 56;
    int w4 = (t % 56) * 4;
    float wql[7], wqs[7], wkl[11], wks[11];
#pragma unroll
    for (int i = 0; i < 7; ++i) { wql[i] = lq[c * 7 + i]; wqs[i] = sq[c * 7 + i]; }
#pragma unroll
    for (int i = 0; i < 11; ++i) { wkl[i] = lk[c * 11 + i]; wks[i] = sk[c * 11 + i]; }
    const float* xb = x + (size_t)(b * CC + c) * PLANE;
    float ql[4] = {0,0,0,0}, qs[4] = {0,0,0,0};
    float kl[4] = {0,0,0,0}, ks[4] = {0,0,0,0};
#pragma unroll
    for (int i = 0; i < 11; ++i) {
        int hh = h + i - 5;                       // k taps: offsets -5..5
        if (hh >= 0 && hh < 224) {
            float4 v = *(const float4*)(xb + hh * 224 + w4);
            float vv[4] = {v.x, v.y, v.z, v.w};
#pragma unroll
            for (int j = 0; j < 4; ++j) { kl[j] += wkl[i] * vv[j]; ks[j] += wks[i] * vv[j]; }
            if (i >= 2 && i <= 8) {               // q taps: offsets -3..3
#pragma unroll
                for (int j = 0; j < 4; ++j) { ql[j] += wql[i-2] * vv[j]; qs[j] += wqs[i-2] * vv[j]; }
            }
        }
    }
    size_t off = (size_t)(b * CC + c) * PLANE + h * 224 + w4;
    *(uint32_t*)(g_Q + off)        = pack4fp8(ql[0], ql[1], ql[2], ql[3]);
    *(uint32_t*)(g_Q + BCHW + off) = pack4fp8(qs[0], qs[1], qs[2], qs[3]);
    *(uint32_t*)(g_K + off)        = pack4fp8(kl[0], kl[1], kl[2], kl[3]);
    *(uint32_t*)(g_K + BCHW + off) = pack4fp8(ks[0], ks[1], ks[2], ks[3]);
}

// -------- conv along W. Same grid/block as convh --------
__global__ __launch_bounds__(256) void convw_kernel(
        const float* __restrict__ x,
        const float* __restrict__ lq, const float* __restrict__ lk,
        const float* __restrict__ sq, const float* __restrict__ sk) {
    int c = blockIdx.y, b = blockIdx.z;
    int t = blockIdx.x * blockDim.x + threadIdx.x;
    int h = t / 56;
    int w4 = (t % 56) * 4;
    float wql[7], wqs[7], wkl[11], wks[11];
#pragma unroll
    for (int i = 0; i < 7; ++i) { wql[i] = lq[c * 7 + i]; wqs[i] = sq[c * 7 + i]; }
#pragma unroll
    for (int i = 0; i < 11; ++i) { wkl[i] = lk[c * 11 + i]; wks[i] = sk[c * 11 + i]; }
    const float* xr = x + (size_t)(b * CC + c) * PLANE + h * 224;
    float buf[20];                                 // x columns [w4-8, w4+11]
#pragma unroll
    for (int i = 0; i < 20; ++i) buf[i] = 0.f;
#pragma unroll
    for (int s = 0; s < 5; ++s) {
        int wb = w4 - 8 + s * 4;
        if (wb >= 0 && wb < 224) {
            float4 v = *(const float4*)(xr + wb);
            buf[s*4+0] = v.x; buf[s*4+1] = v.y; buf[s*4+2] = v.z; buf[s*4+3] = v.w;
        }
    }
    float ql[4], qs[4], kl[4], ks[4];
#pragma unroll
    for (int j = 0; j < 4; ++j) {
        float aql = 0, aqs = 0, akl = 0, aks = 0;
#pragma unroll
        for (int i = 0; i < 11; ++i) { float v = buf[j+i+3]; akl += wkl[i]*v; aks += wks[i]*v; }
#pragma unroll
        for (int i = 0; i < 7; ++i)  { float v = buf[j+i+5]; aql += wql[i]*v; aqs += wqs[i]*v; }
        ql[j] = aql; qs[j] = aqs; kl[j] = akl; ks[j] = aks;
    }
    size_t off = (size_t)(b * CC + c) * PLANE + h * 224 + w4;
    *(uint32_t*)(g_Q + off)        = pack4fp8(ql[0], ql[1], ql[2], ql[3]);
    *(uint32_t*)(g_Q + BCHW + off) = pack4fp8(qs[0], qs[1], qs[2], qs[3]);
    *(uint32_t*)(g_K + off)        = pack4fp8(kl[0], kl[1], kl[2], kl[3]);
    *(uint32_t*)(g_K + BCHW + off) = pack4fp8(ks[0], ks[1], ks[2], ks[3]);
}

// -------- fp8 tensor-core Gram with register double-buffering --------
// grid (NSG, b=8, branch=2), block 256 = 8 warps. Chunk = 128 n (128 B/row),
// rows padded to 144 B (distinct 16B segments mod 128 -> conflict-free ldmatrix).
// mma m16n8k32 e4m3: fragment layout == bf16 m16n8k16 with 4 fp8 per register.
__global__ __launch_bounds__(256) void gram_mma_kernel() {
    int slice = blockIdx.x, b = blockIdx.y, br = blockIdx.z;
    const uint8_t* Qb = g_Q + (size_t)br * BCHW + (size_t)b * CHW;
    const uint8_t* Kb = g_K + (size_t)br * BCHW + (size_t)b * CHW;
    __shared__ __align__(16) uint8_t Qs[64][144];
    __shared__ __align__(16) uint8_t Ks[64][144];
    int t = threadIdx.x;
    int warp = t >> 5, lane = t & 31;
    int wm = (warp & 3) * 16;
    int wn = (warp >> 2) * 32;
    int lr = t >> 2;                 // load row 0..63
    int lo = (t & 3) * 32;           // byte offset {0,32,64,96}
    float acc[4][4] = {};            // [n-tile][c0..c3]
    int n0 = slice * KSG;
    const uint8_t* qrow = Qb + (size_t)lr * PLANE + n0 + lo;
    const uint8_t* krow = Kb + (size_t)lr * PLANE + n0 + lo;

    // preload chunk 0 into registers
    uint4 q0 = *(const uint4*)qrow;
    uint4 q1 = *(const uint4*)(qrow + 16);
    uint4 k0 = *(const uint4*)krow;
    uint4 k1 = *(const uint4*)(krow + 16);

    for (int i = 0; i < NCH; ++i) {
        *(uint4*)&Qs[lr][lo]      = q0;
        *(uint4*)&Qs[lr][lo + 16] = q1;
        *(uint4*)&Ks[lr][lo]      = k0;
        *(uint4*)&Ks[lr][lo + 16] = k1;
        __syncthreads();
        if (i + 1 < NCH) {              // issue next chunk's loads now
            int nb = (i + 1) * 128;
            q0 = *(const uint4*)(qrow + nb);
            q1 = *(const uint4*)(qrow + nb + 16);
            k0 = *(const uint4*)(krow + nb);
            k1 = *(const uint4*)(krow + nb + 16);
        }
#pragma unroll
        for (int ks = 0; ks < 4; ++ks) {           // 4 k32 steps per 128-n chunk
            uint32_t a0, a1, a2, a3;
            uint32_t aaddr = smem_u32(&Qs[wm + (lane & 15)][ks * 32 + ((lane >> 4) & 1) * 16]);
            asm volatile("ldmatrix.sync.aligned.m8n8.x4.shared.b16 {%0,%1,%2,%3}, [%4];"
                         : "=r"(a0), "=r"(a1), "=r"(a2), "=r"(a3) : "r"(aaddr));
#pragma unroll
            for (int nt = 0; nt < 4; ++nt) {
                uint32_t b0, b1;
                uint32_t baddr = smem_u32(&Ks[wn + nt * 8 + (lane & 7)][ks * 32 + ((lane >> 3) & 1) * 16]);
                asm volatile("ldmatrix.sync.aligned.m8n8.x2.shared.b16 {%0,%1}, [%2];"
                             : "=r"(b0), "=r"(b1) : "r"(baddr));
                asm volatile("mma.sync.aligned.m16n8k32.row.col.f32.e4m3.e4m3.f32 "
                             "{%0,%1,%2,%3}, {%4,%5,%6,%7}, {%8,%9}, {%0,%1,%2,%3};"
                             : "+f"(acc[nt][0]), "+f"(acc[nt][1]), "+f"(acc[nt][2]), "+f"(acc[nt][3])
                             : "r"(a0), "r"(a1), "r"(a2), "r"(a3), "r"(b0), "r"(b1));
            }
        }
        __syncthreads();
    }
    float* out = g_P + (((size_t)br * NSG + slice) * 8 + b) * 4096;
    int m0 = wm + (lane >> 2);
    int nn = (lane & 3) * 2;
#pragma unroll
    for (int nt = 0; nt < 4; ++nt) {
        int col = wn + nt * 8 + nn;
        out[m0 * 64 + col]           = acc[nt][0];
        out[m0 * 64 + col + 1]       = acc[nt][1];
        out[(m0 + 8) * 64 + col]     = acc[nt][2];
        out[(m0 + 8) * 64 + col + 1] = acc[nt][3];
    }
}

// -------- reduce partial grams: G64 from branch 0, G8 (block-diag) from branch 1 --------
__global__ __launch_bounds__(256) void reduce_kernel(int dir) {
    int idx = blockIdx.x * blockDim.x + threadIdx.x;   // 0..36863
    if (idx < 32768) {
        float s = 0.f;
        for (int sl = 0; sl < NSG; ++sl)
            s += g_P[((size_t)sl * 8) * 4096 + idx];          // branch 0
        g_G64[dir * 32768 + idx] = s;
    } else {
        int j = idx - 32768;
        if (j < 4096) {                                       // [b][d][e]
            int b = j >> 9, d = (j >> 3) & 63, e = j & 7;
            int col = (d & ~7) | e;
            float s = 0.f;
            for (int sl = 0; sl < NSG; ++sl)
                s += g_P[(((size_t)NSG + sl) * 8 + b) * 4096 + d * 64 + col];  // branch 1
            g_G8[dir * 4096 + j] = s;
        }
    }
}

// -------- finalize: vbar + softmax + mix + sigmoid. grid 8 (b), block 64 --------
__global__ __launch_bounds__(64) void finalize_kernel(
        const float* __restrict__ lvh, const float* __restrict__ lvw,
        const float* __restrict__ svh, const float* __restrict__ svw,
        const float* __restrict__ mix) {
    int b = blockIdx.x;
    int e = threadIdx.x;
    __shared__ float vb[4][64];   // 0:lrb_h 1:lrb_w 2:srb_h 3:srb_w
    for (int pass = 0; pass < 2; ++pass) {
        const float* R = (pass == 0 ? g_R : g_Cs) + (size_t)(b * 64 + e) * 224;
        const float* wl = (pass == 0 ? lvh : lvw) + e * 21;
        const float* ws = (pass == 0 ? svh : svw) + e * 21;
        float T = 0.f;
        for (int h = 0; h < 224; ++h) T += R[h];
        float head[11], tail[11];
        head[0] = 0.f; tail[0] = 0.f;
#pragma unroll
        for (int i = 1; i <= 10; ++i) { head[i] = head[i-1] + R[i-1]; tail[i] = tail[i-1] + R[224-i]; }
        float a0 = 0.f, a1 = 0.f;
#pragma unroll
        for (int t = 0; t < 21; ++t) {
            int d = t - 10;
            float clip = T - (d > 0 ? head[d] : tail[-d]);
            a0 += wl[t] * clip;
            a1 += ws[t] * clip;
        }
        vb[pass][e]     = a0 * (1.f / 50176.f);
        vb[2 + pass][e] = a1 * (1.f / 50176.f);
    }
    __syncthreads();
    int d = threadIdx.x;
    float contrib[4];
#pragma unroll
    for (int dir = 0; dir < 2; ++dir) {
        const float* row = g_G64 + dir * 32768 + b * 4096 + d * 64;
        float m = -1e30f;
        for (int j = 0; j < 64; ++j) m = fmaxf(m, row[j] * 0.125f);
        float s = 0.f, dot = 0.f;
        for (int j = 0; j < 64; ++j) {
            float w = __expf(row[j] * 0.125f - m);
            s += w;
            dot += w * vb[dir][j];
        }
        contrib[dir] = dot / s;
    }
#pragma unroll
    for (int dir = 0; dir < 2; ++dir) {
        const float* row = g_G8 + dir * 4096 + b * 512 + d * 8;
        int base = d & ~7;
        float m = -1e30f;
#pragma unroll
        for (int j = 0; j < 8; ++j) m = fmaxf(m, row[j] * 0.35355339059327373f);
        float s = 0.f, dot = 0.f;
#pragma unroll
        for (int j = 0; j < 8; ++j) {
            float w = __expf(row[j] * 0.35355339059327373f - m);
            s += w;
            dot += w * vb[2 + dir][base + j];
        }
        contrib[2 + dir] = dot / s;
    }
    float a = mix[0] * contrib[0] + mix[1] * contrib[1]
            + mix[2] * contrib[2] + mix[3] * contrib[3];
    g_S[b * 64 + d] = 1.f / (1.f + __expf(-a));
}

// -------- apply gate: out = sigmoid(a)[b,c] * x. grid (49, 512), block 256 --------
__global__ __launch_bounds__(256) void apply_kernel(const float* __restrict__ x,
                                                    float* __restrict__ out) {
    int bc = blockIdx.y;                       // 0..511 = b*64+c
    int i = blockIdx.x * blockDim.x + threadIdx.x;   // 0..12543 (float4 within plane)
    float s = g_S[bc];
    size_t off = (size_t)bc * (PLANE / 4) + i;
    float4 v = ((const float4*)x)[off];
    v.x *= s; v.y *= s; v.z *= s; v.w *= s;
    ((float4*)out)[off] = v;
}

extern "C" void kernel_launch(void* const* d_in, const int* in_sizes, int n_in,
                              void* d_out, int out_size) {
    const float* x      = (const float*)d_in[0];
    const float* lrb_qh = (const float*)d_in[1];
    const float* lrb_qw = (const float*)d_in[2];
    const float* lrb_kh = (const float*)d_in[3];
    const float* lrb_kw = (const float*)d_in[4];
    const float* lrb_vh = (const float*)d_in[5];
    const float* lrb_vw = (const float*)d_in[6];
    const float* srb_qh = (const float*)d_in[7];
    const float* srb_qw = (const float*)d_in[8];
    const float* srb_kh = (const float*)d_in[9];
    const float* srb_kw = (const float*)d_in[10];
    const float* srb_vh = (const float*)d_in[11];
    const float* srb_vw = (const float*)d_in[12];
    const float* mix_w  = (const float*)d_in[13];
    float* out = (float*)d_out;

    sums_kernel<<<dim3(64, 8), 224>>>(x);

    convh_kernel<<<dim3(49, 64, 8), 256>>>(x, lrb_qh, lrb_kh, srb_qh, srb_kh);
    gram_mma_kernel<<<dim3(NSG, 8, 2), 256>>>();
    reduce_kernel<<<144, 256>>>(0);

    convw_kernel<<<dim3(49, 64, 8), 256>>>(x, lrb_qw, lrb_kw, srb_qw, srb_kw);
    gram_mma_kernel<<<dim3(NSG, 8, 2), 256>>>();
    reduce_kernel<<<144, 256>>>(1);

    finalize_kernel<<<8, 64>>>(lrb_vh, lrb_vw, srb_vh, srb_vw, mix_w);
    apply_kernel<<<dim3(49, 512), 256>>>(x, out);
}